// round 9
// baseline (speedup 1.0000x reference)
#include <cuda_runtime.h>
#include <math.h>
#include <stdint.h>

// ---------------- problem constants ----------------
#define BB   16
#define LL   512
#define MMCH 7
#define PP   16
#define SSTR 8
#define NPAT 64
#define DD   4096
#define HHE  32
#define KVH  8
#define HDIM 128
#define DFFN 14336
#define FCN  128
#define PREDN 96
#define BMSEQ (BB*MMCH)        // 112
#define TOK   (BMSEQ*NPAT)     // 7168
#define KFC   (NPAT*DD)        // 262144
#define FCSPLIT 64
#define EPSV 1e-5f

// ---------------- scratch ----------------
__device__ float g_mean[BMSEQ];
__device__ float g_std[BMSEQ];
__device__ float g_h [(size_t)TOK*DD];
__device__ float g_hn[(size_t)TOK*DD];
__device__ float g_q [(size_t)TOK*DD];
__device__ float g_k [(size_t)TOK*KVH*HDIM];
__device__ float g_v [(size_t)TOK*KVH*HDIM];
__device__ float g_o [(size_t)TOK*DD];
__device__ float g_gate[(size_t)TOK*DFFN];
__device__ float g_up  [(size_t)TOK*DFFN];
__device__ float g_zpart[(size_t)FCSPLIT*128*128];
__device__ float g_z[BMSEQ*FCN];
// tf32-rounded weights (1.0 GB)
#define WOFF_Q  0
#define WOFF_K  16777216
#define WOFF_V  20971520
#define WOFF_O  25165824
#define WOFF_G  41943040
#define WOFF_U  100663296
#define WOFF_D  159383552
#define WOFF_FC 218103808
#define WTF_TOTAL 251658240
__device__ float g_wtf[(size_t)WTF_TOTAL];

__device__ __forceinline__ uint32_t f2tf(float f) {
    uint32_t r;
    asm("cvt.rna.tf32.f32 %0, %1;" : "=r"(r) : "f"(f));
    return r;
}
__device__ __forceinline__ float f2tff(float f) { return __uint_as_float(f2tf(f)); }

__device__ __forceinline__ uint32_t smem_u32(const void* p) {
    uint32_t a;
    asm("{ .reg .u64 t; cvta.to.shared.u64 t, %1; cvt.u32.u64 %0, t; }" : "=r"(a) : "l"(p));
    return a;
}
__device__ __forceinline__ void mma_tf32(float c[4], const uint32_t a[4], const uint32_t b[2]) {
    asm volatile("mma.sync.aligned.m16n8k8.row.col.f32.tf32.tf32.f32 "
        "{%0,%1,%2,%3}, {%4,%5,%6,%7}, {%8,%9}, {%0,%1,%2,%3};"
        : "+f"(c[0]), "+f"(c[1]), "+f"(c[2]), "+f"(c[3])
        : "r"(a[0]), "r"(a[1]), "r"(a[2]), "r"(a[3]), "r"(b[0]), "r"(b[1]));
}
#define CP_ASYNC16(dst, src) \
    asm volatile("cp.async.cg.shared.global [%0], [%1], 16;" :: "r"(dst), "l"(src) : "memory")
#define CP_COMMIT() asm volatile("cp.async.commit_group;" ::: "memory")
#define CP_WAIT1()  asm volatile("cp.async.wait_group 1;" ::: "memory")

// ---------------- weight tf32 pre-round ----------------
__global__ void cvtw_kernel(const float4* __restrict__ src, float4* __restrict__ dst, int n4) {
    int i = blockIdx.x*256 + threadIdx.x;
    if (i < n4) {
        float4 v = src[i];
        v.x = f2tff(v.x); v.y = f2tff(v.y); v.z = f2tff(v.z); v.w = f2tff(v.w);
        dst[i] = v;
    }
}

// ---------------- mma.sync TF32 GEMM, cp.async 3-stage, 64x(BN/4) warp tile ----------------
// C[M,N] = A[M,K] @ W[N,K]^T (+epilogue). BM=128, BN template, BK=32.
// 8 warps as 2(M) x 4(N); warp tile 64 x BN/4. Inputs pre-rounded to tf32.
// MODE: 0 plain, 1 add aux (residual), 2 silu(acc)*aux (output rounded to tf32)
#define KSTRIDE 36

template<int BN, int MODE>
__global__ void __launch_bounds__(256, 1)
mma_gemm(const float* __restrict__ A, int lda,
         const float* __restrict__ W, int ldw,
         float* __restrict__ C, int ldc,
         const float* __restrict__ aux,
         int Mtiles, int Ntiles, int Mvalid, int kchunks,
         long ksA, long ksW, long ksC)
{
    constexpr int NB = BN/32;              // B frag count per warp = B cp.async slots
    constexpr int TILEA = 128*KSTRIDE;     // floats
    constexpr int STAGEF = (128+BN)*KSTRIDE;
    constexpr int STAGEB_ = STAGEF*4;      // bytes
    extern __shared__ __align__(16) float smf[];
    const uint32_t sb_u = smem_u32(smf);
    const int tid = threadIdx.x;

    A += (size_t)blockIdx.y * ksA;
    W += (size_t)blockIdx.y * ksW;
    C += (size_t)blockIdx.y * ksC;

    // tile rasterization (GROUP_M=16)
    int mt, nt;
    {
        const int GM = 16;
        int perg = GM * Ntiles;
        int g = blockIdx.x / perg, rem = blockIdx.x % perg;
        int gm = Mtiles - g*GM; if (gm > GM) gm = GM;
        mt = g*GM + rem % gm;
        nt = rem / gm;
    }

    // cp.async addressing: thread covers rows (tid>>3)+32*slot, col16 = tid&7
    const int rowA = tid >> 3, c4 = tid & 7;
    const float* pA[4];
    #pragma unroll
    for (int i = 0; i < 4; i++) {
        int gr = mt*128 + rowA + 32*i; if (gr >= Mvalid) gr = Mvalid-1;
        pA[i] = A + (size_t)gr*lda + c4*4;
    }
    const float* pB0 = W + (size_t)(nt*BN + rowA)*ldw + c4*4;
    const uint32_t soA = (uint32_t)(rowA*KSTRIDE + c4*4)*4;
    const uint32_t soB = (uint32_t)((TILEA + rowA*KSTRIDE + c4*4))*4;
    const uint32_t sstep = (uint32_t)(32*KSTRIDE)*4;

    const int warp = tid >> 5, lane = tid & 31;
    const int wm = warp & 1, wn = warp >> 1;       // 2(M) x 4(N)
    const int gid = lane >> 2, quad = lane & 3;

    float acc[4][NB][4];
    #pragma unroll
    for (int f = 0; f < 4; f++)
        #pragma unroll
        for (int g = 0; g < NB; g++)
            #pragma unroll
            for (int j = 0; j < 4; j++) acc[f][g][j] = 0.f;

    // prologue: stages 0,1
    #pragma unroll
    for (int s = 0; s < 2; s++) {
        uint32_t base = sb_u + (uint32_t)s*STAGEB_;
        #pragma unroll
        for (int i = 0; i < 4; i++) CP_ASYNC16(base + soA + i*sstep, pA[i] + s*32);
        #pragma unroll
        for (int i = 0; i < NB; i++) CP_ASYNC16(base + soB + i*sstep, pB0 + (size_t)i*32*ldw + s*32);
        CP_COMMIT();
    }

    int st = 0;
    for (int kc = 0; kc < kchunks; kc++) {
        CP_WAIT1();
        __syncthreads();
        if (kc + 2 < kchunks) {
            int s2 = st + 2; if (s2 >= 3) s2 -= 3;
            uint32_t base = sb_u + (uint32_t)s2*STAGEB_;
            const long koff = (long)(kc+2)*32;
            #pragma unroll
            for (int i = 0; i < 4; i++) CP_ASYNC16(base + soA + i*sstep, pA[i] + koff);
            #pragma unroll
            for (int i = 0; i < NB; i++) CP_ASYNC16(base + soB + i*sstep, pB0 + (size_t)i*32*ldw + koff);
        }
        CP_COMMIT();
        const uint32_t* sA = (const uint32_t*)(smf + st*STAGEF);
        const uint32_t* sB = sA + TILEA;
        #pragma unroll
        for (int ks = 0; ks < 4; ks++) {
            const int kb = ks*8;
            uint32_t a[4][4];
            #pragma unroll
            for (int f = 0; f < 4; f++) {
                int r0 = wm*64 + f*16 + gid;
                a[f][0] = sA[r0*KSTRIDE + kb + quad];
                a[f][1] = sA[(r0+8)*KSTRIDE + kb + quad];
                a[f][2] = sA[r0*KSTRIDE + kb + quad + 4];
                a[f][3] = sA[(r0+8)*KSTRIDE + kb + quad + 4];
            }
            uint32_t b[NB][2];
            #pragma unroll
            for (int g = 0; g < NB; g++) {
                int nr = wn*(BN/4) + g*8 + gid;
                b[g][0] = sB[nr*KSTRIDE + kb + quad];
                b[g][1] = sB[nr*KSTRIDE + kb + quad + 4];
            }
            #pragma unroll
            for (int f = 0; f < 4; f++)
                #pragma unroll
                for (int g = 0; g < NB; g++)
                    mma_tf32(acc[f][g], a[f], b[g]);
        }
        st = st + 1; if (st == 3) st = 0;
    }

    // epilogue
    #pragma unroll
    for (int f = 0; f < 4; f++) {
        int r0 = mt*128 + wm*64 + f*16 + gid;
        #pragma unroll
        for (int g = 0; g < NB; g++) {
            int col = nt*BN + wn*(BN/4) + g*8 + 2*quad;
            #pragma unroll
            for (int half = 0; half < 2; half++) {
                int row = r0 + half*8;
                if (row >= Mvalid) continue;
                float v0 = acc[f][g][half*2 + 0];
                float v1 = acc[f][g][half*2 + 1];
                size_t off = (size_t)row*ldc + col;
                if (MODE == 1) {
                    v0 += aux[off]; v1 += aux[off+1];
                } else if (MODE == 2) {
                    v0 = f2tff(v0 / (1.f + __expf(-v0)) * aux[off]);
                    v1 = f2tff(v1 / (1.f + __expf(-v1)) * aux[off+1]);
                }
                float2 o; o.x = v0; o.y = v1;
                *(float2*)(C + off) = o;
            }
        }
    }
}

// ---------------- instance norm ----------------
__global__ void instnorm_kernel(const float* __restrict__ x) {
    __shared__ float r1[256], r2[256];
    int bm = blockIdx.x, b = bm / MMCH, m = bm % MMCH, tid = threadIdx.x;
    float s = 0.f, s2 = 0.f;
    for (int l = tid; l < LL; l += 256) {
        float v = x[((size_t)b*LL + l)*MMCH + m];
        s += v; s2 += v*v;
    }
    r1[tid] = s; r2[tid] = s2; __syncthreads();
    for (int o = 128; o; o >>= 1) {
        if (tid < o) { r1[tid] += r1[tid+o]; r2[tid] += r2[tid+o]; }
        __syncthreads();
    }
    if (tid == 0) {
        float mu  = r1[0] / (float)LL;
        float var = r2[0] / (float)LL - mu*mu;
        g_mean[bm] = mu;
        g_std[bm]  = sqrtf(var + EPSV);
    }
}

// ---------------- patch embed ----------------
__global__ void patch_kernel(const float* __restrict__ x, const float* __restrict__ Win,
                             const float* __restrict__ bin) {
    int bmn = blockIdx.x;
    int bm = bmn >> 6, n = bmn & 63;
    int b = bm / MMCH, m = bm % MMCH;
    __shared__ float patch[PP];
    int tid = threadIdx.x;
    if (tid < PP) {
        int l = n*SSTR + tid;
        if (l > LL-1) l = LL-1;
        patch[tid] = (x[((size_t)b*LL + l)*MMCH + m] - g_mean[bm]) / g_std[bm];
    }
    __syncthreads();
    for (int d = tid; d < DD; d += 256) {
        float acc = bin[d];
        const float* wr = Win + (size_t)d*PP;
        #pragma unroll
        for (int p = 0; p < PP; p++) acc += patch[p]*wr[p];
        g_h[(size_t)bmn*DD + d] = acc;
    }
}

// ---------------- RMSNorm (tf32-rounded out) ----------------
__global__ void rmsnorm_kernel(const float* __restrict__ in, const float* __restrict__ w,
                               float* __restrict__ out) {
    __shared__ float red[256];
    int row = blockIdx.x, tid = threadIdx.x;
    const float* r = in + (size_t)row*DD;
    float s = 0.f;
    for (int i = tid; i < DD; i += 256) { float v = r[i]; s += v*v; }
    red[tid] = s; __syncthreads();
    for (int o = 128; o; o >>= 1) { if (tid < o) red[tid] += red[tid+o]; __syncthreads(); }
    float scale = rsqrtf(red[0]/(float)DD + EPSV);
    float* outr = out + (size_t)row*DD;
    for (int i = tid; i < DD; i += 256) outr[i] = f2tff(r[i]*scale*w[i]);
}

// ---------------- RoPE ----------------
__global__ void rope_kernel() {
    int row = blockIdx.x;
    int n = row & 63;
    float* qrow = g_q + (size_t)row*DD;
    float* krow = g_k + (size_t)row*(KVH*HDIM);
    int tid = threadIdx.x;
    const int qpairs = HHE*64;
    const int kpairs = KVH*64;
    for (int i = tid; i < qpairs + kpairs; i += 256) {
        float* base; int hh, d;
        if (i < qpairs) { base = qrow; hh = i >> 6; d = i & 63; }
        else            { int j = i - qpairs; base = krow; hh = j >> 6; d = j & 63; }
        float f = powf(500000.0f, -(float)(2*d) / 128.0f);
        float a = (float)n * f;
        float c = cosf(a), s = sinf(a);
        float t0 = base[hh*HDIM + d];
        float t1 = base[hh*HDIM + d + 64];
        base[hh*HDIM + d]      = t0*c - t1*s;
        base[hh*HDIM + d + 64] = t1*c + t0*s;
    }
}

// ---------------- attention (tf32-rounded out) ----------------
__global__ void attn_kernel() {
    extern __shared__ float sm[];
    float* Qs = sm;
    float* Ks = Qs + 64*128;
    float* Vs = Ks + 128*65;
    float* Ss = Vs + 64*128;
    int bm = blockIdx.x, h = blockIdx.y, kvh = h >> 2;
    int tid = threadIdx.x;
    for (int i = tid; i < 64*128; i += 256) {
        int n = i >> 7, d = i & 127;
        size_t tok = (size_t)(bm*64 + n);
        Qs[i] = g_q[tok*DD + h*HDIM + d];
        Ks[d*65 + n] = g_k[tok*(KVH*HDIM) + kvh*HDIM + d];
        Vs[i] = g_v[tok*(KVH*HDIM) + kvh*HDIM + d];
    }
    __syncthreads();
    const float scale = 0.08838834764831845f;
    for (int i = tid; i < 64*64; i += 256) {
        int qi = i >> 6, ki = i & 63;
        float acc;
        if (ki <= qi) {
            acc = 0.f;
            #pragma unroll 8
            for (int d = 0; d < 128; d++) acc += Qs[qi*128 + d]*Ks[d*65 + ki];
            acc *= scale;
        } else acc = -1e9f;
        Ss[qi*65 + ki] = acc;
    }
    __syncthreads();
    if (tid < 64) {
        float mx = -1e30f;
        for (int k = 0; k < 64; k++) mx = fmaxf(mx, Ss[tid*65 + k]);
        float sum = 0.f;
        for (int k = 0; k < 64; k++) { float e = expf(Ss[tid*65 + k] - mx); Ss[tid*65 + k] = e; sum += e; }
        float inv = 1.f / sum;
        for (int k = 0; k < 64; k++) Ss[tid*65 + k] *= inv;
    }
    __syncthreads();
    for (int i = tid; i < 64*128; i += 256) {
        int qi = i >> 7, d = i & 127;
        float acc = 0.f;
        #pragma unroll 8
        for (int k = 0; k < 64; k++) acc += Ss[qi*65 + k]*Vs[k*128 + d];
        g_o[(size_t)(bm*64 + qi)*DD + h*HDIM + d] = f2tff(acc);
    }
}

// ---------------- FC reduce + head ----------------
__global__ void zreduce_kernel(const float* __restrict__ bfc) {
    int idx = blockIdx.x*256 + threadIdx.x;
    if (idx >= BMSEQ*FCN) return;
    int f = idx & 127, bm = idx >> 7;
    float acc = bfc[f];
    for (int ks = 0; ks < FCSPLIT; ks++) acc += g_zpart[(size_t)ks*16384 + bm*128 + f];
    g_z[idx] = acc;
}

__global__ void head_kernel(const float* __restrict__ Wout, const float* __restrict__ bout,
                            float* __restrict__ out) {
    __shared__ float zr[FCN];
    int bm = blockIdx.x, tid = threadIdx.x;
    if (tid < FCN) {
        float v = g_z[bm*FCN + tid];
        zr[tid] = v > 0.f ? v : 0.01f*v;
    }
    __syncthreads();
    if (tid < PREDN) {
        float acc = bout[tid];
        const float* wr = Wout + (size_t)tid*FCN;
        #pragma unroll 8
        for (int f = 0; f < FCN; f++) acc += zr[f]*wr[f];
        int b = bm / MMCH, m = bm % MMCH;
        out[(size_t)b*(PREDN*MMCH) + tid*MMCH + m] = acc*g_std[bm] + g_mean[bm];
    }
}

// ---------------- host ----------------
extern "C" void kernel_launch(void* const* d_in, const int* in_sizes, int n_in,
                              void* d_out, int out_size) {
    const float* x      = (const float*)d_in[0];
    const float* W_in   = (const float*)d_in[1];
    const float* b_in   = (const float*)d_in[2];
    const float* attn_w = (const float*)d_in[3];
    const float* Wq     = (const float*)d_in[4];
    const float* Wk     = (const float*)d_in[5];
    const float* Wv     = (const float*)d_in[6];
    const float* Wo     = (const float*)d_in[7];
    const float* mlp_w  = (const float*)d_in[8];
    const float* Wg     = (const float*)d_in[9];
    const float* Wu     = (const float*)d_in[10];
    const float* Wd     = (const float*)d_in[11];
    const float* fin_w  = (const float*)d_in[12];
    const float* W_fc   = (const float*)d_in[13];
    const float* b_fc   = (const float*)d_in[14];
    const float* W_out  = (const float*)d_in[15];
    const float* b_out  = (const float*)d_in[16];
    float* out = (float*)d_out;

    float *ph, *phn, *pq, *pk, *pv, *po, *pg, *pu, *pzp, *pw;
    cudaGetSymbolAddress((void**)&ph,  g_h);
    cudaGetSymbolAddress((void**)&phn, g_hn);
    cudaGetSymbolAddress((void**)&pq,  g_q);
    cudaGetSymbolAddress((void**)&pk,  g_k);
    cudaGetSymbolAddress((void**)&pv,  g_v);
    cudaGetSymbolAddress((void**)&po,  g_o);
    cudaGetSymbolAddress((void**)&pg,  g_gate);
    cudaGetSymbolAddress((void**)&pu,  g_up);
    cudaGetSymbolAddress((void**)&pzp, g_zpart);
    cudaGetSymbolAddress((void**)&pw,  g_wtf);

    const int attn_smem = (64*128 + 128*65 + 64*128 + 64*65) * (int)sizeof(float);
    cudaFuncSetAttribute(attn_kernel, cudaFuncAttributeMaxDynamicSharedMemorySize, attn_smem);
    const int sm256 = 3 * (128+256)*KSTRIDE*4;   // 165888
    const int sm128 = 3 * (128+128)*KSTRIDE*4;   // 110592
    cudaFuncSetAttribute(mma_gemm<256,0>, cudaFuncAttributeMaxDynamicSharedMemorySize, sm256);
    cudaFuncSetAttribute(mma_gemm<256,1>, cudaFuncAttributeMaxDynamicSharedMemorySize, sm256);
    cudaFuncSetAttribute(mma_gemm<256,2>, cudaFuncAttributeMaxDynamicSharedMemorySize, sm256);
    cudaFuncSetAttribute(mma_gemm<128,0>, cudaFuncAttributeMaxDynamicSharedMemorySize, sm128);

    // 0. pre-round all GEMM weights to tf32
    {
        struct { const float* src; long off; int cnt; } ws[8] = {
            {Wq, WOFF_Q, 16777216}, {Wk, WOFF_K, 4194304}, {Wv, WOFF_V, 4194304},
            {Wo, WOFF_O, 16777216}, {Wg, WOFF_G, 58720256}, {Wu, WOFF_U, 58720256},
            {Wd, WOFF_D, 58720256}, {W_fc, WOFF_FC, 33554432}
        };
        for (int i = 0; i < 8; i++) {
            int n4 = ws[i].cnt / 4;
            cvtw_kernel<<<(n4 + 255)/256, 256>>>((const float4*)ws[i].src,
                                                 (float4*)(pw + ws[i].off), n4);
        }
    }
    const float* tWq = pw + WOFF_Q;  const float* tWk = pw + WOFF_K;
    const float* tWv = pw + WOFF_V;  const float* tWo = pw + WOFF_O;
    const float* tWg = pw + WOFF_G;  const float* tWu = pw + WOFF_U;
    const float* tWd = pw + WOFF_D;  const float* tWfc = pw + WOFF_FC;

    // 1. RevIN stats
    instnorm_kernel<<<BMSEQ, 256>>>(x);
    // 2. patch embed
    patch_kernel<<<TOK, 256>>>(x, W_in, b_in);
    // 3. attn RMSNorm
    rmsnorm_kernel<<<TOK, 256>>>(ph, attn_w, phn);
    // 4-6. q/k/v projections (BN=256 tiles). K/V: N=1024 -> Ntiles=4.
    {
        dim3 gq(56*16, 1);
        mma_gemm<256,0><<<gq, 256, sm256>>>(phn, DD, tWq, DD, pq, DD, nullptr,
                                            56, 16, TOK, DD/32, 0, 0, 0);
        dim3 gk(56*4, 1);
        mma_gemm<256,0><<<gk, 256, sm256>>>(phn, DD, tWk, DD, pk, KVH*HDIM, nullptr,
                                            56, 4, TOK, DD/32, 0, 0, 0);
        mma_gemm<256,0><<<gk, 256, sm256>>>(phn, DD, tWv, DD, pv, KVH*HDIM, nullptr,
                                            56, 4, TOK, DD/32, 0, 0, 0);
    }
    // 7. RoPE
    rope_kernel<<<TOK, 256>>>();
    // 8. attention
    {
        dim3 grid(BMSEQ, HHE);
        attn_kernel<<<grid, 256, attn_smem>>>();
    }
    // 9. output proj + residual
    {
        dim3 g(56*16, 1);
        mma_gemm<256,1><<<g, 256, sm256>>>(po, DD, tWo, DD, ph, DD, ph,
                                           56, 16, TOK, DD/32, 0, 0, 0);
    }
    // 10. mlp RMSNorm
    rmsnorm_kernel<<<TOK, 256>>>(ph, mlp_w, phn);
    // 11. up proj, 12. gate proj fused silu*up
    {
        dim3 g(56*56, 1);
        mma_gemm<256,0><<<g, 256, sm256>>>(phn, DD, tWu, DD, pu, DFFN, nullptr,
                                           56, 56, TOK, DD/32, 0, 0, 0);
        mma_gemm<256,2><<<g, 256, sm256>>>(phn, DD, tWg, DD, pg, DFFN, pu,
                                           56, 56, TOK, DD/32, 0, 0, 0);
    }
    // 13. down proj + residual
    {
        dim3 g(56*16, 1);
        mma_gemm<256,1><<<g, 256, sm256>>>(pg, DFFN, tWd, DFFN, ph, DD, ph,
                                           56, 16, TOK, DFFN/32, 0, 0, 0);
    }
    // 14. final RMSNorm
    rmsnorm_kernel<<<TOK, 256>>>(ph, fin_w, phn);
    // 15. FC head: split-K tf32 GEMM (BN=128)
    {
        dim3 g(1, FCSPLIT);
        mma_gemm<128,0><<<g, 256, sm128>>>(phn, KFC, tWfc, KFC, pzp, 128, nullptr,
                                           1, 1, 112, (KFC/FCSPLIT)/32,
                                           KFC/FCSPLIT, KFC/FCSPLIT, 128*128);
    }
    // 16. reduce + 17. head
    zreduce_kernel<<<(BMSEQ*FCN + 255)/256, 256>>>(b_fc);
    head_kernel<<<BMSEQ, 128>>>(W_out, b_out, out);
}

// round 11
// speedup vs baseline: 1.1550x; 1.1550x over previous
#include <cuda_runtime.h>
#include <cuda_fp16.h>
#include <math.h>
#include <stdint.h>

// ---------------- problem constants ----------------
#define BB   16
#define LL   512
#define MMCH 7
#define PP   16
#define SSTR 8
#define NPAT 64
#define DD   4096
#define HHE  32
#define KVH  8
#define HDIM 128
#define DFFN 14336
#define FCN  128
#define PREDN 96
#define BMSEQ (BB*MMCH)        // 112
#define TOK   (BMSEQ*NPAT)     // 7168
#define KFC   (NPAT*DD)        // 262144
#define FCSPLIT 64
#define EPSV 1e-5f

// ---------------- scratch ----------------
__device__ float g_mean[BMSEQ];
__device__ float g_std[BMSEQ];
__device__ float g_h [(size_t)TOK*DD];
__device__ __half g_hn[(size_t)TOK*DD];
__device__ float g_q [(size_t)TOK*DD];
__device__ float g_k [(size_t)TOK*KVH*HDIM];
__device__ float g_v [(size_t)TOK*KVH*HDIM];
__device__ __half g_o [(size_t)TOK*DD];
__device__ __half g_gate[(size_t)TOK*DFFN];
__device__ float  g_up  [(size_t)TOK*DFFN];
__device__ float g_zpart[(size_t)FCSPLIT*128*128];
__device__ float g_z[BMSEQ*FCN];
// fp16 weights (0.5 GB)
#define WOFF_Q  0
#define WOFF_K  16777216
#define WOFF_V  20971520
#define WOFF_O  25165824
#define WOFF_G  41943040
#define WOFF_U  100663296
#define WOFF_D  159383552
#define WOFF_FC 218103808
#define WTF_TOTAL 251658240
__device__ __half g_wtf[(size_t)WTF_TOTAL];

__device__ __forceinline__ uint32_t smem_u32(const void* p) {
    uint32_t a;
    asm("{ .reg .u64 t; cvta.to.shared.u64 t, %1; cvt.u32.u64 %0, t; }" : "=r"(a) : "l"(p));
    return a;
}
__device__ __forceinline__ void mma_f16(float c[4], const uint32_t a[4], const uint32_t b[2]) {
    asm volatile("mma.sync.aligned.m16n8k16.row.col.f32.f16.f16.f32 "
        "{%0,%1,%2,%3}, {%4,%5,%6,%7}, {%8,%9}, {%0,%1,%2,%3};"
        : "+f"(c[0]), "+f"(c[1]), "+f"(c[2]), "+f"(c[3])
        : "r"(a[0]), "r"(a[1]), "r"(a[2]), "r"(a[3]), "r"(b[0]), "r"(b[1]));
}
#define CP_ASYNC16(dst, src) \
    asm volatile("cp.async.cg.shared.global [%0], [%1], 16;" :: "r"(dst), "l"(src) : "memory")
#define CP_COMMIT() asm volatile("cp.async.commit_group;" ::: "memory")
#define CP_WAIT1()  asm volatile("cp.async.wait_group 1;" ::: "memory")

// ---------------- weight fp16 convert ----------------
__global__ void cvtw_kernel(const float4* __restrict__ src, __half2* __restrict__ dst, int n4) {
    int i = blockIdx.x*256 + threadIdx.x;
    if (i < n4) {
        float4 v = src[i];
        dst[2*i]   = __floats2half2_rn(v.x, v.y);
        dst[2*i+1] = __floats2half2_rn(v.z, v.w);
    }
}

// ---------------- fp16 mma GEMM, cp.async 3-stage, 128x128 tile, 32x64 warp tile ----------------
// C[M,N] = A[M,K] @ W[N,K]^T (+epilogue). BM=BN=128, BK=32 halfs.
// 8 warps 4(M)x2(N). MODE: 0 C=float, 1 C=float+aux, 2 C=half silu(acc)*aux
#define KSH 40                 // SMEM row stride in halfs
#define TILEA_H (128*KSH)      // 5120 halfs
#define STAGE_H (256*KSH)      // 10240 halfs
#define STAGEB  (STAGE_H*2)    // 20480 bytes

template<int MODE>
__global__ void __launch_bounds__(256, 2)
hgemm(const __half* __restrict__ A, int lda,
      const __half* __restrict__ W, int ldw,
      void* __restrict__ Cv, int ldc,
      const float* __restrict__ aux,
      int Mtiles, int Ntiles, int Mvalid, int kchunks,
      long ksA, long ksW, long ksC)
{
    extern __shared__ __align__(16) __half smh[];
    const uint32_t sb_u = smem_u32(smh);
    const int tid = threadIdx.x;

    A += (size_t)blockIdx.y * ksA;
    W += (size_t)blockIdx.y * ksW;

    // tile rasterization (GROUP_M=16)
    int mt, nt;
    {
        const int GM = 16;
        int perg = GM * Ntiles;
        int g = blockIdx.x / perg, rem = blockIdx.x % perg;
        int gm = Mtiles - g*GM; if (gm > GM) gm = GM;
        mt = g*GM + rem % gm;
        nt = rem / gm;
    }

    // cp.async: thread -> one row (A rows 0-127, B rows 128-255), 4x16B segs/row/chunk
    const __half* gsrc;
    uint32_t srow;
    if (tid < 128) {
        int gr = mt*128 + tid; if (gr >= Mvalid) gr = Mvalid-1;
        gsrc = A + (size_t)gr*lda;
        srow = (uint32_t)tid*(KSH*2);
    } else {
        gsrc = W + (size_t)(nt*128 + (tid-128))*ldw;
        srow = (uint32_t)(TILEA_H*2) + (uint32_t)(tid-128)*(KSH*2);
    }

    const int warp = tid >> 5, lane = tid & 31;
    const int wm = warp & 3, wn = warp >> 2;       // 4(M) x 2(N)
    const int gid = lane >> 2, quad = lane & 3;

    float acc[2][8][4];
    #pragma unroll
    for (int f = 0; f < 2; f++)
        #pragma unroll
        for (int g = 0; g < 8; g++)
            #pragma unroll
            for (int j = 0; j < 4; j++) acc[f][g][j] = 0.f;

    // prologue: stages 0,1
    #pragma unroll
    for (int s = 0; s < 2; s++) {
        uint32_t base = sb_u + (uint32_t)s*STAGEB + srow;
        #pragma unroll
        for (int i = 0; i < 4; i++) CP_ASYNC16(base + i*16, gsrc + s*32 + i*8);
        CP_COMMIT();
    }

    int st = 0;
    for (int kc = 0; kc < kchunks; kc++) {
        CP_WAIT1();
        __syncthreads();
        if (kc + 2 < kchunks) {
            int s2 = st + 2; if (s2 >= 3) s2 -= 3;
            uint32_t base = sb_u + (uint32_t)s2*STAGEB + srow;
            const __half* gk = gsrc + (size_t)(kc+2)*32;
            #pragma unroll
            for (int i = 0; i < 4; i++) CP_ASYNC16(base + i*16, gk + i*8);
        }
        CP_COMMIT();
        const uint32_t* sA32 = (const uint32_t*)(smh + (size_t)st*STAGE_H);
        const uint32_t* sB32 = sA32 + TILEA_H/2;
        #pragma unroll
        for (int ks = 0; ks < 2; ks++) {
            const int kb = ks*8;
            uint32_t a[2][4];
            #pragma unroll
            for (int f = 0; f < 2; f++) {
                int r0 = wm*32 + f*16 + gid;
                a[f][0] = sA32[r0*(KSH/2) + kb + quad];
                a[f][1] = sA32[(r0+8)*(KSH/2) + kb + quad];
                a[f][2] = sA32[r0*(KSH/2) + kb + quad + 4];
                a[f][3] = sA32[(r0+8)*(KSH/2) + kb + quad + 4];
            }
            uint32_t b[8][2];
            #pragma unroll
            for (int g = 0; g < 8; g++) {
                int nr = wn*64 + g*8 + gid;
                b[g][0] = sB32[nr*(KSH/2) + kb + quad];
                b[g][1] = sB32[nr*(KSH/2) + kb + quad + 4];
            }
            #pragma unroll
            for (int f = 0; f < 2; f++)
                #pragma unroll
                for (int g = 0; g < 8; g++)
                    mma_f16(acc[f][g], a[f], b[g]);
        }
        st = st + 1; if (st == 3) st = 0;
    }

    // epilogue
    #pragma unroll
    for (int f = 0; f < 2; f++) {
        int r0 = mt*128 + wm*32 + f*16 + gid;
        #pragma unroll
        for (int g = 0; g < 8; g++) {
            int col = nt*128 + wn*64 + g*8 + 2*quad;
            #pragma unroll
            for (int half_ = 0; half_ < 2; half_++) {
                int row = r0 + half_*8;
                if (row >= Mvalid) continue;
                float v0 = acc[f][g][half_*2 + 0];
                float v1 = acc[f][g][half_*2 + 1];
                size_t off = (size_t)row*ldc + col + (size_t)blockIdx.y*0;
                if (MODE == 2) {
                    v0 = v0 / (1.f + __expf(-v0)) * aux[off];
                    v1 = v1 / (1.f + __expf(-v1)) * aux[off+1];
                    *(__half2*)((__half*)Cv + off) = __floats2half2_rn(v0, v1);
                } else {
                    if (MODE == 1) { v0 += aux[off]; v1 += aux[off+1]; }
                    float* C = (float*)Cv + (size_t)blockIdx.y*ksC;
                    float2 o; o.x = v0; o.y = v1;
                    *(float2*)(C + off) = o;
                }
            }
        }
    }
}

// ---------------- instance norm ----------------
__global__ void instnorm_kernel(const float* __restrict__ x) {
    __shared__ float r1[256], r2[256];
    int bm = blockIdx.x, b = bm / MMCH, m = bm % MMCH, tid = threadIdx.x;
    float s = 0.f, s2 = 0.f;
    for (int l = tid; l < LL; l += 256) {
        float v = x[((size_t)b*LL + l)*MMCH + m];
        s += v; s2 += v*v;
    }
    r1[tid] = s; r2[tid] = s2; __syncthreads();
    for (int o = 128; o; o >>= 1) {
        if (tid < o) { r1[tid] += r1[tid+o]; r2[tid] += r2[tid+o]; }
        __syncthreads();
    }
    if (tid == 0) {
        float mu  = r1[0] / (float)LL;
        float var = r2[0] / (float)LL - mu*mu;
        g_mean[bm] = mu;
        g_std[bm]  = sqrtf(var + EPSV);
    }
}

// ---------------- patch embed ----------------
__global__ void patch_kernel(const float* __restrict__ x, const float* __restrict__ Win,
                             const float* __restrict__ bin) {
    int bmn = blockIdx.x;
    int bm = bmn >> 6, n = bmn & 63;
    int b = bm / MMCH, m = bm % MMCH;
    __shared__ float patch[PP];
    int tid = threadIdx.x;
    if (tid < PP) {
        int l = n*SSTR + tid;
        if (l > LL-1) l = LL-1;
        patch[tid] = (x[((size_t)b*LL + l)*MMCH + m] - g_mean[bm]) / g_std[bm];
    }
    __syncthreads();
    for (int d = tid; d < DD; d += 256) {
        float acc = bin[d];
        const float* wr = Win + (size_t)d*PP;
        #pragma unroll
        for (int p = 0; p < PP; p++) acc += patch[p]*wr[p];
        g_h[(size_t)bmn*DD + d] = acc;
    }
}

// ---------------- RMSNorm (fp16 out) ----------------
__global__ void rmsnorm_kernel(const float* __restrict__ in, const float* __restrict__ w,
                               __half* __restrict__ out) {
    __shared__ float red[256];
    int row = blockIdx.x, tid = threadIdx.x;
    const float* r = in + (size_t)row*DD;
    float s = 0.f;
    for (int i = tid; i < DD; i += 256) { float v = r[i]; s += v*v; }
    red[tid] = s; __syncthreads();
    for (int o = 128; o; o >>= 1) { if (tid < o) red[tid] += red[tid+o]; __syncthreads(); }
    float scale = rsqrtf(red[0]/(float)DD + EPSV);
    __half* outr = out + (size_t)row*DD;
    for (int i = tid; i < DD; i += 256) outr[i] = __float2half_rn(r[i]*scale*w[i]);
}

// ---------------- RoPE ----------------
__global__ void rope_kernel() {
    int row = blockIdx.x;
    int n = row & 63;
    float* qrow = g_q + (size_t)row*DD;
    float* krow = g_k + (size_t)row*(KVH*HDIM);
    int tid = threadIdx.x;
    const int qpairs = HHE*64;
    const int kpairs = KVH*64;
    for (int i = tid; i < qpairs + kpairs; i += 256) {
        float* base; int hh, d;
        if (i < qpairs) { base = qrow; hh = i >> 6; d = i & 63; }
        else            { int j = i - qpairs; base = krow; hh = j >> 6; d = j & 63; }
        float f = powf(500000.0f, -(float)(2*d) / 128.0f);
        float a = (float)n * f;
        float c = cosf(a), s = sinf(a);
        float t0 = base[hh*HDIM + d];
        float t1 = base[hh*HDIM + d + 64];
        base[hh*HDIM + d]      = t0*c - t1*s;
        base[hh*HDIM + d + 64] = t1*c + t0*s;
    }
}

// ---------------- attention (fp16 out) ----------------
__global__ void attn_kernel() {
    extern __shared__ float sm[];
    float* Qs = sm;
    float* Ks = Qs + 64*128;
    float* Vs = Ks + 128*65;
    float* Ss = Vs + 64*128;
    int bm = blockIdx.x, h = blockIdx.y, kvh = h >> 2;
    int tid = threadIdx.x;
    for (int i = tid; i < 64*128; i += 256) {
        int n = i >> 7, d = i & 127;
        size_t tok = (size_t)(bm*64 + n);
        Qs[i] = g_q[tok*DD + h*HDIM + d];
        Ks[d*65 + n] = g_k[tok*(KVH*HDIM) + kvh*HDIM + d];
        Vs[i] = g_v[tok*(KVH*HDIM) + kvh*HDIM + d];
    }
    __syncthreads();
    const float scale = 0.08838834764831845f;
    for (int i = tid; i < 64*64; i += 256) {
        int qi = i >> 6, ki = i & 63;
        float acc;
        if (ki <= qi) {
            acc = 0.f;
            #pragma unroll 8
            for (int d = 0; d < 128; d++) acc += Qs[qi*128 + d]*Ks[d*65 + ki];
            acc *= scale;
        } else acc = -1e9f;
        Ss[qi*65 + ki] = acc;
    }
    __syncthreads();
    if (tid < 64) {
        float mx = -1e30f;
        for (int k = 0; k < 64; k++) mx = fmaxf(mx, Ss[tid*65 + k]);
        float sum = 0.f;
        for (int k = 0; k < 64; k++) { float e = expf(Ss[tid*65 + k] - mx); Ss[tid*65 + k] = e; sum += e; }
        float inv = 1.f / sum;
        for (int k = 0; k < 64; k++) Ss[tid*65 + k] *= inv;
    }
    __syncthreads();
    for (int i = tid; i < 64*128; i += 256) {
        int qi = i >> 7, d = i & 127;
        float acc = 0.f;
        #pragma unroll 8
        for (int k = 0; k < 64; k++) acc += Ss[qi*65 + k]*Vs[k*128 + d];
        g_o[(size_t)(bm*64 + qi)*DD + h*HDIM + d] = __float2half_rn(acc);
    }
}

// ---------------- FC reduce + head ----------------
__global__ void zreduce_kernel(const float* __restrict__ bfc) {
    int idx = blockIdx.x*256 + threadIdx.x;
    if (idx >= BMSEQ*FCN) return;
    int f = idx & 127, bm = idx >> 7;
    float acc = bfc[f];
    for (int ks = 0; ks < FCSPLIT; ks++) acc += g_zpart[(size_t)ks*16384 + bm*128 + f];
    g_z[idx] = acc;
}

__global__ void head_kernel(const float* __restrict__ Wout, const float* __restrict__ bout,
                            float* __restrict__ out) {
    __shared__ float zr[FCN];
    int bm = blockIdx.x, tid = threadIdx.x;
    if (tid < FCN) {
        float v = g_z[bm*FCN + tid];
        zr[tid] = v > 0.f ? v : 0.01f*v;
    }
    __syncthreads();
    if (tid < PREDN) {
        float acc = bout[tid];
        const float* wr = Wout + (size_t)tid*FCN;
        #pragma unroll 8
        for (int f = 0; f < FCN; f++) acc += zr[f]*wr[f];
        int b = bm / MMCH, m = bm % MMCH;
        out[(size_t)b*(PREDN*MMCH) + tid*MMCH + m] = acc*g_std[bm] + g_mean[bm];
    }
}

// ---------------- host ----------------
extern "C" void kernel_launch(void* const* d_in, const int* in_sizes, int n_in,
                              void* d_out, int out_size) {
    const float* x      = (const float*)d_in[0];
    const float* W_in   = (const float*)d_in[1];
    const float* b_in   = (const float*)d_in[2];
    const float* attn_w = (const float*)d_in[3];
    const float* Wq     = (const float*)d_in[4];
    const float* Wk     = (const float*)d_in[5];
    const float* Wv     = (const float*)d_in[6];
    const float* Wo     = (const float*)d_in[7];
    const float* mlp_w  = (const float*)d_in[8];
    const float* Wg     = (const float*)d_in[9];
    const float* Wu     = (const float*)d_in[10];
    const float* Wd     = (const float*)d_in[11];
    const float* fin_w  = (const float*)d_in[12];
    const float* W_fc   = (const float*)d_in[13];
    const float* b_fc   = (const float*)d_in[14];
    const float* W_out  = (const float*)d_in[15];
    const float* b_out  = (const float*)d_in[16];
    float* out = (float*)d_out;

    float *ph, *pq, *pk, *pv, *pu, *pzp;
    __half *phn, *po, *pg, *pw;
    cudaGetSymbolAddress((void**)&ph,  g_h);
    cudaGetSymbolAddress((void**)&phn, g_hn);
    cudaGetSymbolAddress((void**)&pq,  g_q);
    cudaGetSymbolAddress((void**)&pk,  g_k);
    cudaGetSymbolAddress((void**)&pv,  g_v);
    cudaGetSymbolAddress((void**)&po,  g_o);
    cudaGetSymbolAddress((void**)&pg,  g_gate);
    cudaGetSymbolAddress((void**)&pu,  g_up);
    cudaGetSymbolAddress((void**)&pzp, g_zpart);
    cudaGetSymbolAddress((void**)&pw,  g_wtf);

    const int attn_smem = (64*128 + 128*65 + 64*128 + 64*65) * (int)sizeof(float);
    cudaFuncSetAttribute(attn_kernel, cudaFuncAttributeMaxDynamicSharedMemorySize, attn_smem);
    const int gsmem = 3 * STAGEB;   // 61440
    cudaFuncSetAttribute(hgemm<0>, cudaFuncAttributeMaxDynamicSharedMemorySize, gsmem);
    cudaFuncSetAttribute(hgemm<1>, cudaFuncAttributeMaxDynamicSharedMemorySize, gsmem);
    cudaFuncSetAttribute(hgemm<2>, cudaFuncAttributeMaxDynamicSharedMemorySize, gsmem);

    // 0. convert all GEMM weights to fp16
    {
        struct { const float* src; long off; int cnt; } ws[8] = {
            {Wq, WOFF_Q, 16777216}, {Wk, WOFF_K, 4194304}, {Wv, WOFF_V, 4194304},
            {Wo, WOFF_O, 16777216}, {Wg, WOFF_G, 58720256}, {Wu, WOFF_U, 58720256},
            {Wd, WOFF_D, 58720256}, {W_fc, WOFF_FC, 33554432}
        };
        for (int i = 0; i < 8; i++) {
            int n4 = ws[i].cnt / 4;
            cvtw_kernel<<<(n4 + 255)/256, 256>>>((const float4*)ws[i].src,
                                                 (__half2*)(pw + ws[i].off), n4);
        }
    }
    const __half* tWq = pw + WOFF_Q;  const __half* tWk = pw + WOFF_K;
    const __half* tWv = pw + WOFF_V;  const __half* tWo = pw + WOFF_O;
    const __half* tWg = pw + WOFF_G;  const __half* tWu = pw + WOFF_U;
    const __half* tWd = pw + WOFF_D;  const __half* tWfc = pw + WOFF_FC;

    // 1. RevIN stats
    instnorm_kernel<<<BMSEQ, 256>>>(x);
    // 2. patch embed
    patch_kernel<<<TOK, 256>>>(x, W_in, b_in);
    // 3. attn RMSNorm -> fp16
    rmsnorm_kernel<<<TOK, 256>>>(ph, attn_w, phn);
    // 4-6. q/k/v projections
    {
        dim3 gq(56*32, 1);
        hgemm<0><<<gq, 256, gsmem>>>(phn, DD, tWq, DD, pq, DD, nullptr,
                                     56, 32, TOK, DD/32, 0, 0, 0);
        dim3 gk(56*8, 1);
        hgemm<0><<<gk, 256, gsmem>>>(phn, DD, tWk, DD, pk, KVH*HDIM, nullptr,
                                     56, 8, TOK, DD/32, 0, 0, 0);
        hgemm<0><<<gk, 256, gsmem>>>(phn, DD, tWv, DD, pv, KVH*HDIM, nullptr,
                                     56, 8, TOK, DD/32, 0, 0, 0);
    }
    // 7. RoPE
    rope_kernel<<<TOK, 256>>>();
    // 8. attention -> fp16 o
    {
        dim3 grid(BMSEQ, HHE);
        attn_kernel<<<grid, 256, attn_smem>>>();
    }
    // 9. output proj + residual
    {
        dim3 g(56*32, 1);
        hgemm<1><<<g, 256, gsmem>>>(po, DD, tWo, DD, ph, DD, ph,
                                    56, 32, TOK, DD/32, 0, 0, 0);
    }
    // 10. mlp RMSNorm -> fp16
    rmsnorm_kernel<<<TOK, 256>>>(ph, mlp_w, phn);
    // 11. up proj (fp32 out), 12. gate proj fused silu*up (fp16 out)
    {
        dim3 g(56*112, 1);
        hgemm<0><<<g, 256, gsmem>>>(phn, DD, tWu, DD, pu, DFFN, nullptr,
                                    56, 112, TOK, DD/32, 0, 0, 0);
        hgemm<2><<<g, 256, gsmem>>>(phn, DD, tWg, DD, pg, DFFN, pu,
                                    56, 112, TOK, DD/32, 0, 0, 0);
    }
    // 13. down proj + residual
    {
        dim3 g(56*32, 1);
        hgemm<1><<<g, 256, gsmem>>>(pg, DFFN, tWd, DFFN, ph, DD, ph,
                                    56, 32, TOK, DFFN/32, 0, 0, 0);
    }
    // 14. final RMSNorm -> fp16
    rmsnorm_kernel<<<TOK, 256>>>(ph, fin_w, phn);
    // 15. FC head: split-K fp16 GEMM
    {
        dim3 g(1, FCSPLIT);
        hgemm<0><<<g, 256, gsmem>>>(phn, KFC, tWfc, KFC, pzp, 128, nullptr,
                                    1, 1, 112, (KFC/FCSPLIT)/32,
                                    KFC/FCSPLIT, KFC/FCSPLIT, 128*128);
    }
    // 16. reduce + 17. head
    zreduce_kernel<<<(BMSEQ*FCN + 255)/256, 256>>>(b_fc);
    head_kernel<<<BMSEQ, 128>>>(W_out, b_out, out);
}

// round 12
// speedup vs baseline: 1.3628x; 1.1800x over previous
#include <cuda_runtime.h>
#include <cuda_fp16.h>
#include <math.h>
#include <stdint.h>

// ---------------- problem constants ----------------
#define BB   16
#define LL   512
#define MMCH 7
#define PP   16
#define SSTR 8
#define NPAT 64
#define DD   4096
#define HHE  32
#define KVH  8
#define HDIM 128
#define DFFN 14336
#define FCN  128
#define PREDN 96
#define BMSEQ (BB*MMCH)        // 112
#define TOK   (BMSEQ*NPAT)     // 7168
#define KFC   (NPAT*DD)        // 262144
#define QKVN  6144
#define FCSPLIT 64
#define EPSV 1e-5f

// ---------------- scratch ----------------
__device__ float g_mean[BMSEQ];
__device__ float g_std[BMSEQ];
__device__ float g_h [(size_t)TOK*DD];
__device__ __half g_hn[(size_t)TOK*DD];
__device__ float g_qkv[(size_t)TOK*QKVN];
__device__ __half g_o [(size_t)TOK*DD];
__device__ __half g_gate[(size_t)TOK*DFFN];
__device__ float  g_up  [(size_t)TOK*DFFN];
__device__ float g_zpart[(size_t)FCSPLIT*128*128];
__device__ float g_z[BMSEQ*FCN];
// fp16 weights (0.5 GB); Q,K,V contiguous -> fused QKV GEMM
#define WOFF_Q  0
#define WOFF_K  16777216
#define WOFF_V  20971520
#define WOFF_O  25165824
#define WOFF_G  41943040
#define WOFF_U  100663296
#define WOFF_D  159383552
#define WOFF_FC 218103808
#define WTF_TOTAL 251658240
__device__ __half g_wtf[(size_t)WTF_TOTAL];

__device__ __forceinline__ uint32_t smem_u32(const void* p) {
    uint32_t a;
    asm("{ .reg .u64 t; cvta.to.shared.u64 t, %1; cvt.u32.u64 %0, t; }" : "=r"(a) : "l"(p));
    return a;
}
__device__ __forceinline__ void mma_f16(float c[4], const uint32_t a[4], const uint32_t b[2]) {
    asm volatile("mma.sync.aligned.m16n8k16.row.col.f32.f16.f16.f32 "
        "{%0,%1,%2,%3}, {%4,%5,%6,%7}, {%8,%9}, {%0,%1,%2,%3};"
        : "+f"(c[0]), "+f"(c[1]), "+f"(c[2]), "+f"(c[3])
        : "r"(a[0]), "r"(a[1]), "r"(a[2]), "r"(a[3]), "r"(b[0]), "r"(b[1]));
}
#define LDSM_X4(r0,r1,r2,r3,addr) \
    asm volatile("ldmatrix.sync.aligned.m8n8.x4.shared.b16 {%0,%1,%2,%3}, [%4];" \
        : "=r"(r0), "=r"(r1), "=r"(r2), "=r"(r3) : "r"(addr))
#define CP_ASYNC16(dst, src) \
    asm volatile("cp.async.cg.shared.global [%0], [%1], 16;" :: "r"(dst), "l"(src) : "memory")
#define CP_COMMIT() asm volatile("cp.async.commit_group;" ::: "memory")
#define CP_WAIT2()  asm volatile("cp.async.wait_group 2;" ::: "memory")

// ---------------- weight fp16 convert ----------------
__global__ void cvtw_kernel(const float4* __restrict__ src, __half2* __restrict__ dst, int n4) {
    int i = blockIdx.x*256 + threadIdx.x;
    if (i < n4) {
        float4 v = src[i];
        dst[2*i]   = __floats2half2_rn(v.x, v.y);
        dst[2*i+1] = __floats2half2_rn(v.z, v.w);
    }
}

// ---------------- fp16 mma GEMM: ldmatrix + cp.async 4-stage ----------------
// C[M,N] = A[M,K] @ W[N,K]^T (+epilogue). BM=BN=128, BK=32 halfs.
// 8 warps 4(M)x2(N), warp tile 32x64. MODE: 0 C=float, 1 C=float+aux, 2 C=half silu*aux
#define KSH 40                 // SMEM row stride in halfs
#define TILEA_H (128*KSH)      // 5120 halfs
#define STAGE_H (256*KSH)      // 10240 halfs
#define STAGEB  (STAGE_H*2)    // 20480 bytes
#define NSTG 4

template<int MODE>
__global__ void __launch_bounds__(256, 2)
hgemm(const __half* __restrict__ A, int lda,
      const __half* __restrict__ W, int ldw,
      void* __restrict__ Cv, int ldc,
      const float* __restrict__ aux,
      int Mtiles, int Ntiles, int Mvalid, int kchunks,
      long ksA, long ksW, long ksC)
{
    extern __shared__ __align__(16) __half smh[];
    const uint32_t sb_u = smem_u32(smh);
    const int tid = threadIdx.x;

    A += (size_t)blockIdx.y * ksA;
    W += (size_t)blockIdx.y * ksW;

    // tile rasterization (GROUP_M=16)
    int mt, nt;
    {
        const int GM = 16;
        int perg = GM * Ntiles;
        int g = blockIdx.x / perg, rem = blockIdx.x % perg;
        int gm = Mtiles - g*GM; if (gm > GM) gm = GM;
        mt = g*GM + rem % gm;
        nt = rem / gm;
    }

    // cp.async: thread -> one row (A rows 0-127, B rows 128-255), 4x16B/row/chunk
    const __half* gsrc;
    uint32_t srow;
    if (tid < 128) {
        int gr = mt*128 + tid; if (gr >= Mvalid) gr = Mvalid-1;
        gsrc = A + (size_t)gr*lda;
        srow = (uint32_t)tid*(KSH*2);
    } else {
        gsrc = W + (size_t)(nt*128 + (tid-128))*ldw;
        srow = (uint32_t)(TILEA_H*2) + (uint32_t)(tid-128)*(KSH*2);
    }

    const int warp = tid >> 5, lane = tid & 31;
    const int wm = warp & 3, wn = warp >> 2;       // 4(M) x 2(N)
    const int gid = lane >> 2, quad = lane & 3;

    // ldmatrix addresses (stage 0 base, bytes)
    uint32_t aAddr[2], bAddr[4];
    #pragma unroll
    for (int f = 0; f < 2; f++)
        aAddr[f] = sb_u + (uint32_t)(((wm*32 + f*16 + (lane & 15))*KSH + (lane >> 4)*8) * 2);
    #pragma unroll
    for (int p = 0; p < 4; p++)
        bAddr[p] = sb_u + (uint32_t)((TILEA_H + (wn*64 + p*16 + (lane & 7) + ((lane >> 4) << 3))*KSH
                                      + ((lane >> 3) & 1)*8) * 2);

    float acc[2][8][4];
    #pragma unroll
    for (int f = 0; f < 2; f++)
        #pragma unroll
        for (int g = 0; g < 8; g++)
            #pragma unroll
            for (int j = 0; j < 4; j++) acc[f][g][j] = 0.f;

    // prologue: stages 0,1,2
    #pragma unroll
    for (int s = 0; s < 3; s++) {
        uint32_t base = sb_u + (uint32_t)s*STAGEB + srow;
        #pragma unroll
        for (int i = 0; i < 4; i++) CP_ASYNC16(base + i*16, gsrc + s*32 + i*8);
        CP_COMMIT();
    }

    int st = 0;
    for (int kc = 0; kc < kchunks; kc++) {
        CP_WAIT2();
        __syncthreads();
        if (kc + 3 < kchunks) {
            int s3 = st + 3; if (s3 >= NSTG) s3 -= NSTG;
            uint32_t base = sb_u + (uint32_t)s3*STAGEB + srow;
            const __half* gk = gsrc + (size_t)(kc+3)*32;
            #pragma unroll
            for (int i = 0; i < 4; i++) CP_ASYNC16(base + i*16, gk + i*8);
        }
        CP_COMMIT();
        const uint32_t stOff = (uint32_t)st*STAGEB;
        #pragma unroll
        for (int ks = 0; ks < 2; ks++) {
            const uint32_t koff = stOff + ks*32;
            uint32_t a[2][4];
            LDSM_X4(a[0][0], a[0][1], a[0][2], a[0][3], aAddr[0] + koff);
            LDSM_X4(a[1][0], a[1][1], a[1][2], a[1][3], aAddr[1] + koff);
            uint32_t b[8][2];
            #pragma unroll
            for (int p = 0; p < 4; p++)
                LDSM_X4(b[2*p][0], b[2*p][1], b[2*p+1][0], b[2*p+1][1], bAddr[p] + koff);
            #pragma unroll
            for (int f = 0; f < 2; f++)
                #pragma unroll
                for (int g = 0; g < 8; g++)
                    mma_f16(acc[f][g], a[f], b[g]);
        }
        st = st + 1; if (st == NSTG) st = 0;
    }

    // epilogue
    #pragma unroll
    for (int f = 0; f < 2; f++) {
        int r0 = mt*128 + wm*32 + f*16 + gid;
        #pragma unroll
        for (int g = 0; g < 8; g++) {
            int col = nt*128 + wn*64 + g*8 + 2*quad;
            #pragma unroll
            for (int half_ = 0; half_ < 2; half_++) {
                int row = r0 + half_*8;
                if (row >= Mvalid) continue;
                float v0 = acc[f][g][half_*2 + 0];
                float v1 = acc[f][g][half_*2 + 1];
                size_t off = (size_t)row*ldc + col;
                if (MODE == 2) {
                    v0 = v0 / (1.f + __expf(-v0)) * aux[off];
                    v1 = v1 / (1.f + __expf(-v1)) * aux[off+1];
                    *(__half2*)((__half*)Cv + off) = __floats2half2_rn(v0, v1);
                } else {
                    if (MODE == 1) { v0 += aux[off]; v1 += aux[off+1]; }
                    float* C = (float*)Cv + (size_t)blockIdx.y*ksC;
                    float2 o; o.x = v0; o.y = v1;
                    *(float2*)(C + off) = o;
                }
            }
        }
    }
}

// ---------------- instance norm ----------------
__global__ void instnorm_kernel(const float* __restrict__ x) {
    __shared__ float r1[256], r2[256];
    int bm = blockIdx.x, b = bm / MMCH, m = bm % MMCH, tid = threadIdx.x;
    float s = 0.f, s2 = 0.f;
    for (int l = tid; l < LL; l += 256) {
        float v = x[((size_t)b*LL + l)*MMCH + m];
        s += v; s2 += v*v;
    }
    r1[tid] = s; r2[tid] = s2; __syncthreads();
    for (int o = 128; o; o >>= 1) {
        if (tid < o) { r1[tid] += r1[tid+o]; r2[tid] += r2[tid+o]; }
        __syncthreads();
    }
    if (tid == 0) {
        float mu  = r1[0] / (float)LL;
        float var = r2[0] / (float)LL - mu*mu;
        g_mean[bm] = mu;
        g_std[bm]  = sqrtf(var + EPSV);
    }
}

// ---------------- patch embed ----------------
__global__ void patch_kernel(const float* __restrict__ x, const float* __restrict__ Win,
                             const float* __restrict__ bin) {
    int bmn = blockIdx.x;
    int bm = bmn >> 6, n = bmn & 63;
    int b = bm / MMCH, m = bm % MMCH;
    __shared__ float patch[PP];
    int tid = threadIdx.x;
    if (tid < PP) {
        int l = n*SSTR + tid;
        if (l > LL-1) l = LL-1;
        patch[tid] = (x[((size_t)b*LL + l)*MMCH + m] - g_mean[bm]) / g_std[bm];
    }
    __syncthreads();
    for (int d = tid; d < DD; d += 256) {
        float acc = bin[d];
        const float* wr = Win + (size_t)d*PP;
        #pragma unroll
        for (int p = 0; p < PP; p++) acc += patch[p]*wr[p];
        g_h[(size_t)bmn*DD + d] = acc;
    }
}

// ---------------- RMSNorm (fp16 out) ----------------
__global__ void rmsnorm_kernel(const float* __restrict__ in, const float* __restrict__ w,
                               __half* __restrict__ out) {
    __shared__ float red[256];
    int row = blockIdx.x, tid = threadIdx.x;
    const float* r = in + (size_t)row*DD;
    float s = 0.f;
    for (int i = tid; i < DD; i += 256) { float v = r[i]; s += v*v; }
    red[tid] = s; __syncthreads();
    for (int o = 128; o; o >>= 1) { if (tid < o) red[tid] += red[tid+o]; __syncthreads(); }
    float scale = rsqrtf(red[0]/(float)DD + EPSV);
    __half* outr = out + (size_t)row*DD;
    for (int i = tid; i < DD; i += 256) outr[i] = __float2half_rn(r[i]*scale*w[i]);
}

// ---------------- RoPE (on packed qkv) ----------------
__global__ void rope_kernel() {
    int row = blockIdx.x;
    int n = row & 63;
    float* base_q = g_qkv + (size_t)row*QKVN;
    float* base_k = base_q + 4096;
    int tid = threadIdx.x;
    const int qpairs = HHE*64;
    const int kpairs = KVH*64;
    for (int i = tid; i < qpairs + kpairs; i += 256) {
        float* base; int hh, d;
        if (i < qpairs) { base = base_q; hh = i >> 6; d = i & 63; }
        else            { int j = i - qpairs; base = base_k; hh = j >> 6; d = j & 63; }
        float f = powf(500000.0f, -(float)(2*d) / 128.0f);
        float a = (float)n * f;
        float c = cosf(a), s = sinf(a);
        float t0 = base[hh*HDIM + d];
        float t1 = base[hh*HDIM + d + 64];
        base[hh*HDIM + d]      = t0*c - t1*s;
        base[hh*HDIM + d + 64] = t1*c + t0*s;
    }
}

// ---------------- attention (packed qkv in, fp16 out) ----------------
__global__ void attn_kernel() {
    extern __shared__ float sm[];
    float* Qs = sm;
    float* Ks = Qs + 64*128;
    float* Vs = Ks + 128*65;
    float* Ss = Vs + 64*128;
    int bm = blockIdx.x, h = blockIdx.y, kvh = h >> 2;
    int tid = threadIdx.x;
    for (int i = tid; i < 64*128; i += 256) {
        int n = i >> 7, d = i & 127;
        size_t base = (size_t)(bm*64 + n)*QKVN;
        Qs[i] = g_qkv[base + h*HDIM + d];
        Ks[d*65 + n] = g_qkv[base + 4096 + kvh*HDIM + d];
        Vs[i] = g_qkv[base + 5120 + kvh*HDIM + d];
    }
    __syncthreads();
    const float scale = 0.08838834764831845f;
    for (int i = tid; i < 64*64; i += 256) {
        int qi = i >> 6, ki = i & 63;
        float acc;
        if (ki <= qi) {
            acc = 0.f;
            #pragma unroll 8
            for (int d = 0; d < 128; d++) acc += Qs[qi*128 + d]*Ks[d*65 + ki];
            acc *= scale;
        } else acc = -1e9f;
        Ss[qi*65 + ki] = acc;
    }
    __syncthreads();
    if (tid < 64) {
        float mx = -1e30f;
        for (int k = 0; k < 64; k++) mx = fmaxf(mx, Ss[tid*65 + k]);
        float sum = 0.f;
        for (int k = 0; k < 64; k++) { float e = expf(Ss[tid*65 + k] - mx); Ss[tid*65 + k] = e; sum += e; }
        float inv = 1.f / sum;
        for (int k = 0; k < 64; k++) Ss[tid*65 + k] *= inv;
    }
    __syncthreads();
    for (int i = tid; i < 64*128; i += 256) {
        int qi = i >> 7, d = i & 127;
        float acc = 0.f;
        #pragma unroll 8
        for (int k = 0; k < 64; k++) acc += Ss[qi*65 + k]*Vs[k*128 + d];
        g_o[(size_t)(bm*64 + qi)*DD + h*HDIM + d] = __float2half_rn(acc);
    }
}

// ---------------- FC reduce + head ----------------
__global__ void zreduce_kernel(const float* __restrict__ bfc) {
    int idx = blockIdx.x*256 + threadIdx.x;
    if (idx >= BMSEQ*FCN) return;
    int f = idx & 127, bm = idx >> 7;
    float acc = bfc[f];
    for (int ks = 0; ks < FCSPLIT; ks++) acc += g_zpart[(size_t)ks*16384 + bm*128 + f];
    g_z[idx] = acc;
}

__global__ void head_kernel(const float* __restrict__ Wout, const float* __restrict__ bout,
                            float* __restrict__ out) {
    __shared__ float zr[FCN];
    int bm = blockIdx.x, tid = threadIdx.x;
    if (tid < FCN) {
        float v = g_z[bm*FCN + tid];
        zr[tid] = v > 0.f ? v : 0.01f*v;
    }
    __syncthreads();
    if (tid < PREDN) {
        float acc = bout[tid];
        const float* wr = Wout + (size_t)tid*FCN;
        #pragma unroll 8
        for (int f = 0; f < FCN; f++) acc += zr[f]*wr[f];
        int b = bm / MMCH, m = bm % MMCH;
        out[(size_t)b*(PREDN*MMCH) + tid*MMCH + m] = acc*g_std[bm] + g_mean[bm];
    }
}

// ---------------- host ----------------
extern "C" void kernel_launch(void* const* d_in, const int* in_sizes, int n_in,
                              void* d_out, int out_size) {
    const float* x      = (const float*)d_in[0];
    const float* W_in   = (const float*)d_in[1];
    const float* b_in   = (const float*)d_in[2];
    const float* attn_w = (const float*)d_in[3];
    const float* Wq     = (const float*)d_in[4];
    const float* Wk     = (const float*)d_in[5];
    const float* Wv     = (const float*)d_in[6];
    const float* Wo     = (const float*)d_in[7];
    const float* mlp_w  = (const float*)d_in[8];
    const float* Wg     = (const float*)d_in[9];
    const float* Wu     = (const float*)d_in[10];
    const float* Wd     = (const float*)d_in[11];
    const float* fin_w  = (const float*)d_in[12];
    const float* W_fc   = (const float*)d_in[13];
    const float* b_fc   = (const float*)d_in[14];
    const float* W_out  = (const float*)d_in[15];
    const float* b_out  = (const float*)d_in[16];
    float* out = (float*)d_out;

    float *ph, *pqkv, *pu, *pzp;
    __half *phn, *po, *pg, *pw;
    cudaGetSymbolAddress((void**)&ph,   g_h);
    cudaGetSymbolAddress((void**)&phn,  g_hn);
    cudaGetSymbolAddress((void**)&pqkv, g_qkv);
    cudaGetSymbolAddress((void**)&po,   g_o);
    cudaGetSymbolAddress((void**)&pg,   g_gate);
    cudaGetSymbolAddress((void**)&pu,   g_up);
    cudaGetSymbolAddress((void**)&pzp,  g_zpart);
    cudaGetSymbolAddress((void**)&pw,   g_wtf);

    const int attn_smem = (64*128 + 128*65 + 64*128 + 64*65) * (int)sizeof(float);
    cudaFuncSetAttribute(attn_kernel, cudaFuncAttributeMaxDynamicSharedMemorySize, attn_smem);
    const int gsmem = NSTG * STAGEB;   // 81920
    cudaFuncSetAttribute(hgemm<0>, cudaFuncAttributeMaxDynamicSharedMemorySize, gsmem);
    cudaFuncSetAttribute(hgemm<1>, cudaFuncAttributeMaxDynamicSharedMemorySize, gsmem);
    cudaFuncSetAttribute(hgemm<2>, cudaFuncAttributeMaxDynamicSharedMemorySize, gsmem);

    // 0. convert all GEMM weights to fp16 (Q,K,V land contiguously)
    {
        struct { const float* src; long off; int cnt; } ws[8] = {
            {Wq, WOFF_Q, 16777216}, {Wk, WOFF_K, 4194304}, {Wv, WOFF_V, 4194304},
            {Wo, WOFF_O, 16777216}, {Wg, WOFF_G, 58720256}, {Wu, WOFF_U, 58720256},
            {Wd, WOFF_D, 58720256}, {W_fc, WOFF_FC, 33554432}
        };
        for (int i = 0; i < 8; i++) {
            int n4 = ws[i].cnt / 4;
            cvtw_kernel<<<(n4 + 255)/256, 256>>>((const float4*)ws[i].src,
                                                 (__half2*)(pw + ws[i].off), n4);
        }
    }
    const __half* tWqkv = pw + WOFF_Q;
    const __half* tWo = pw + WOFF_O;
    const __half* tWg = pw + WOFF_G;  const __half* tWu = pw + WOFF_U;
    const __half* tWd = pw + WOFF_D;  const __half* tWfc = pw + WOFF_FC;

    // 1. RevIN stats
    instnorm_kernel<<<BMSEQ, 256>>>(x);
    // 2. patch embed
    patch_kernel<<<TOK, 256>>>(x, W_in, b_in);
    // 3. attn RMSNorm -> fp16
    rmsnorm_kernel<<<TOK, 256>>>(ph, attn_w, phn);
    // 4. fused QKV projection (N=6144)
    {
        dim3 g(56*(QKVN/128), 1);
        hgemm<0><<<g, 256, gsmem>>>(phn, DD, tWqkv, DD, pqkv, QKVN, nullptr,
                                    56, QKVN/128, TOK, DD/32, 0, 0, 0);
    }
    // 5. RoPE
    rope_kernel<<<TOK, 256>>>();
    // 6. attention -> fp16 o
    {
        dim3 grid(BMSEQ, HHE);
        attn_kernel<<<grid, 256, attn_smem>>>();
    }
    // 7. output proj + residual
    {
        dim3 g(56*32, 1);
        hgemm<1><<<g, 256, gsmem>>>(po, DD, tWo, DD, ph, DD, ph,
                                    56, 32, TOK, DD/32, 0, 0, 0);
    }
    // 8. mlp RMSNorm -> fp16
    rmsnorm_kernel<<<TOK, 256>>>(ph, mlp_w, phn);
    // 9. up proj (fp32 out), 10. gate proj fused silu*up (fp16 out)
    {
        dim3 g(56*112, 1);
        hgemm<0><<<g, 256, gsmem>>>(phn, DD, tWu, DD, pu, DFFN, nullptr,
                                    56, 112, TOK, DD/32, 0, 0, 0);
        hgemm<2><<<g, 256, gsmem>>>(phn, DD, tWg, DD, pg, DFFN, pu,
                                    56, 112, TOK, DD/32, 0, 0, 0);
    }
    // 11. down proj + residual
    {
        dim3 g(56*32, 1);
        hgemm<1><<<g, 256, gsmem>>>(pg, DFFN, tWd, DFFN, ph, DD, ph,
                                    56, 32, TOK, DFFN/32, 0, 0, 0);
    }
    // 12. final RMSNorm -> fp16
    rmsnorm_kernel<<<TOK, 256>>>(ph, fin_w, phn);
    // 13. FC head: split-K fp16 GEMM
    {
        dim3 g(1, FCSPLIT);
        hgemm<0><<<g, 256, gsmem>>>(phn, KFC, tWfc, KFC, pzp, 128, nullptr,
                                    1, 1, 112, (KFC/FCSPLIT)/32,
                                    KFC/FCSPLIT, KFC/FCSPLIT, 128*128);
    }
    // 14. reduce + 15. head
    zreduce_kernel<<<(BMSEQ*FCN + 255)/256, 256>>>(b_fc);
    head_kernel<<<BMSEQ, 128>>>(W_out, b_out, out);
}

// round 14
// speedup vs baseline: 1.3692x; 1.0047x over previous
#include <cuda_runtime.h>
#include <cuda_fp16.h>
#include <math.h>
#include <stdint.h>

// ---------------- problem constants ----------------
#define BB   16
#define LL   512
#define MMCH 7
#define PP   16
#define SSTR 8
#define NPAT 64
#define DD   4096
#define HHE  32
#define KVH  8
#define HDIM 128
#define DFFN 14336
#define FCN  128
#define PREDN 96
#define BMSEQ (BB*MMCH)        // 112
#define TOK   (BMSEQ*NPAT)     // 7168
#define KFC   (NPAT*DD)        // 262144
#define QKVN  6144
#define FCSPLIT 128
#define EPSV 1e-5f

// ---------------- scratch ----------------
__device__ float g_mean[BMSEQ];
__device__ float g_std[BMSEQ];
__device__ float g_h [(size_t)TOK*DD];
__device__ __half g_hn[(size_t)TOK*DD];
__device__ float g_qkv[(size_t)TOK*QKVN];
__device__ __half g_o [(size_t)TOK*DD];
__device__ __half g_gate[(size_t)TOK*DFFN];
__device__ __half g_up  [(size_t)TOK*DFFN];
__device__ float g_zpart[(size_t)FCSPLIT*128*128];
__device__ float g_z[BMSEQ*FCN];
// fp16 weights (0.5 GB); Q,K,V contiguous -> fused QKV GEMM
#define WOFF_Q  0
#define WOFF_K  16777216
#define WOFF_V  20971520
#define WOFF_O  25165824
#define WOFF_G  41943040
#define WOFF_U  100663296
#define WOFF_D  159383552
#define WOFF_FC 218103808
#define WTF_TOTAL 251658240
__device__ __half g_wtf[(size_t)WTF_TOTAL];

__device__ __forceinline__ uint32_t smem_u32(const void* p) {
    uint32_t a;
    asm("{ .reg .u64 t; cvta.to.shared.u64 t, %1; cvt.u32.u64 %0, t; }" : "=r"(a) : "l"(p));
    return a;
}
__device__ __forceinline__ void mma_f16(float c[4], const uint32_t a[4], const uint32_t b[2]) {
    asm volatile("mma.sync.aligned.m16n8k16.row.col.f32.f16.f16.f32 "
        "{%0,%1,%2,%3}, {%4,%5,%6,%7}, {%8,%9}, {%0,%1,%2,%3};"
        : "+f"(c[0]), "+f"(c[1]), "+f"(c[2]), "+f"(c[3])
        : "r"(a[0]), "r"(a[1]), "r"(a[2]), "r"(a[3]), "r"(b[0]), "r"(b[1]));
}
#define LDSM_X4(r0,r1,r2,r3,addr) \
    asm volatile("ldmatrix.sync.aligned.m8n8.x4.shared.b16 {%0,%1,%2,%3}, [%4];" \
        : "=r"(r0), "=r"(r1), "=r"(r2), "=r"(r3) : "r"(addr))
#define CP_ASYNC16(dst, src) \
    asm volatile("cp.async.cg.shared.global [%0], [%1], 16;" :: "r"(dst), "l"(src) : "memory")
#define CP_COMMIT() asm volatile("cp.async.commit_group;" ::: "memory")
#define CP_WAIT2()  asm volatile("cp.async.wait_group 2;" ::: "memory")

// ---------------- weight fp16 convert (2 launches; segment dispatch at compile time) ----------------
__device__ __forceinline__ void cvt_store(__half2* dst, int i, float4 v) {
    dst[2*i]   = __floats2half2_rn(v.x, v.y);
    dst[2*i+1] = __floats2half2_rn(v.z, v.w);
}
__global__ void cvtw_a(const float4* __restrict__ q, const float4* __restrict__ k,
                       const float4* __restrict__ v, const float4* __restrict__ o) {
    int i = blockIdx.x*256 + threadIdx.x;          // float4 index in [0, WOFF_G/4)
    __half2* dst = (__half2*)g_wtf;
    if      (i <  4194304) cvt_store(dst, i, q[i]);
    else if (i <  5242880) cvt_store(dst, i, k[i - 4194304]);
    else if (i <  6291456) cvt_store(dst, i, v[i - 5242880]);
    else if (i < 10485760) cvt_store(dst, i, o[i - 6291456]);
}
__global__ void cvtw_b(const float4* __restrict__ g, const float4* __restrict__ u,
                       const float4* __restrict__ d, const float4* __restrict__ fc) {
    int i = blockIdx.x*256 + threadIdx.x;          // float4 index in [0, (WTF_TOTAL-WOFF_G)/4)
    __half2* dst = (__half2*)(g_wtf + WOFF_G);
    if      (i < 14680064) cvt_store(dst, i, g[i]);
    else if (i < 29360128) cvt_store(dst, i, u[i - 14680064]);
    else if (i < 44040192) cvt_store(dst, i, d[i - 29360128]);
    else if (i < 52428800) cvt_store(dst, i, fc[i - 44040192]);
}

// ---------------- fp16 mma GEMM: ldmatrix + cp.async 4-stage ----------------
// C[M,N] = A[M,K] @ W[N,K]^T (+epilogue). BM=BN=128, BK=32 halfs.
// 8 warps 4(M)x2(N), warp tile 32x64.
// MODE: 0 C=float, 1 C=float + auxFloat, 2 C=half silu(acc)*auxHalf, 3 C=half
#define KSH 40                 // SMEM row stride in halfs
#define TILEA_H (128*KSH)      // 5120 halfs
#define STAGE_H (256*KSH)      // 10240 halfs
#define STAGEB  (STAGE_H*2)    // 20480 bytes
#define NSTG 4

template<int MODE>
__global__ void __launch_bounds__(256, 2)
hgemm(const __half* __restrict__ A, int lda,
      const __half* __restrict__ W, int ldw,
      void* __restrict__ Cv, int ldc,
      const void* __restrict__ aux,
      int Mtiles, int Ntiles, int Mvalid, int kchunks,
      long ksA, long ksW, long ksC)
{
    extern __shared__ __align__(16) __half smh[];
    const uint32_t sb_u = smem_u32(smh);
    const int tid = threadIdx.x;

    A += (size_t)blockIdx.y * ksA;
    W += (size_t)blockIdx.y * ksW;

    // tile rasterization (GROUP_M=16)
    int mt, nt;
    {
        const int GM = 16;
        int perg = GM * Ntiles;
        int g = blockIdx.x / perg, rem = blockIdx.x % perg;
        int gm = Mtiles - g*GM; if (gm > GM) gm = GM;
        mt = g*GM + rem % gm;
        nt = rem / gm;
    }

    // cp.async: thread -> one row (A rows 0-127, B rows 128-255), 4x16B/row/chunk
    const __half* gsrc;
    uint32_t srow;
    if (tid < 128) {
        int gr = mt*128 + tid; if (gr >= Mvalid) gr = Mvalid-1;
        gsrc = A + (size_t)gr*lda;
        srow = (uint32_t)tid*(KSH*2);
    } else {
        gsrc = W + (size_t)(nt*128 + (tid-128))*ldw;
        srow = (uint32_t)(TILEA_H*2) + (uint32_t)(tid-128)*(KSH*2);
    }

    const int warp = tid >> 5, lane = tid & 31;
    const int wm = warp & 3, wn = warp >> 2;       // 4(M) x 2(N)
    const int gid = lane >> 2, quad = lane & 3;

    // ldmatrix addresses (stage 0 base, bytes)
    uint32_t aAddr[2], bAddr[4];
    #pragma unroll
    for (int f = 0; f < 2; f++)
        aAddr[f] = sb_u + (uint32_t)(((wm*32 + f*16 + (lane & 15))*KSH + (lane >> 4)*8) * 2);
    #pragma unroll
    for (int p = 0; p < 4; p++)
        bAddr[p] = sb_u + (uint32_t)((TILEA_H + (wn*64 + p*16 + (lane & 7) + ((lane >> 4) << 3))*KSH
                                      + ((lane >> 3) & 1)*8) * 2);

    float acc[2][8][4];
    #pragma unroll
    for (int f = 0; f < 2; f++)
        #pragma unroll
        for (int g = 0; g < 8; g++)
            #pragma unroll
            for (int j = 0; j < 4; j++) acc[f][g][j] = 0.f;

    // prologue: stages 0,1,2
    #pragma unroll
    for (int s = 0; s < 3; s++) {
        uint32_t base = sb_u + (uint32_t)s*STAGEB + srow;
        #pragma unroll
        for (int i = 0; i < 4; i++) CP_ASYNC16(base + i*16, gsrc + s*32 + i*8);
        CP_COMMIT();
    }

    int st = 0;
    for (int kc = 0; kc < kchunks; kc++) {
        CP_WAIT2();
        __syncthreads();
        if (kc + 3 < kchunks) {
            int s3 = st + 3; if (s3 >= NSTG) s3 -= NSTG;
            uint32_t base = sb_u + (uint32_t)s3*STAGEB + srow;
            const __half* gk = gsrc + (size_t)(kc+3)*32;
            #pragma unroll
            for (int i = 0; i < 4; i++) CP_ASYNC16(base + i*16, gk + i*8);
        }
        CP_COMMIT();
        const uint32_t stOff = (uint32_t)st*STAGEB;
        #pragma unroll
        for (int ks = 0; ks < 2; ks++) {
            const uint32_t koff = stOff + ks*32;
            uint32_t a[2][4];
            LDSM_X4(a[0][0], a[0][1], a[0][2], a[0][3], aAddr[0] + koff);
            LDSM_X4(a[1][0], a[1][1], a[1][2], a[1][3], aAddr[1] + koff);
            uint32_t b[8][2];
            #pragma unroll
            for (int p = 0; p < 4; p++)
                LDSM_X4(b[2*p][0], b[2*p][1], b[2*p+1][0], b[2*p+1][1], bAddr[p] + koff);
            #pragma unroll
            for (int f = 0; f < 2; f++)
                #pragma unroll
                for (int g = 0; g < 8; g++)
                    mma_f16(acc[f][g], a[f], b[g]);
        }
        st = st + 1; if (st == NSTG) st = 0;
    }

    // epilogue
    #pragma unroll
    for (int f = 0; f < 2; f++) {
        int r0 = mt*128 + wm*32 + f*16 + gid;
        #pragma unroll
        for (int g = 0; g < 8; g++) {
            int col = nt*128 + wn*64 + g*8 + 2*quad;
            #pragma unroll
            for (int half_ = 0; half_ < 2; half_++) {
                int row = r0 + half_*8;
                if (row >= Mvalid) continue;
                float v0 = acc[f][g][half_*2 + 0];
                float v1 = acc[f][g][half_*2 + 1];
                size_t off = (size_t)row*ldc + col;
                if (MODE == 2) {
                    __half2 uh = *(const __half2*)((const __half*)aux + off);
                    float2 uf = __half22float2(uh);
                    v0 = v0 / (1.f + __expf(-v0)) * uf.x;
                    v1 = v1 / (1.f + __expf(-v1)) * uf.y;
                    *(__half2*)((__half*)Cv + off) = __floats2half2_rn(v0, v1);
                } else if (MODE == 3) {
                    *(__half2*)((__half*)Cv + off) = __floats2half2_rn(v0, v1);
                } else {
                    if (MODE == 1) {
                        const float* ax = (const float*)aux;
                        v0 += ax[off]; v1 += ax[off+1];
                    }
                    float* C = (float*)Cv + (size_t)blockIdx.y*ksC;
                    float2 o; o.x = v0; o.y = v1;
                    *(float2*)(C + off) = o;
                }
            }
        }
    }
}

// ---------------- instance norm ----------------
__global__ void instnorm_kernel(const float* __restrict__ x) {
    __shared__ float r1[256], r2[256];
    int bm = blockIdx.x, b = bm / MMCH, m = bm % MMCH, tid = threadIdx.x;
    float s = 0.f, s2 = 0.f;
    for (int l = tid; l < LL; l += 256) {
        float v = x[((size_t)b*LL + l)*MMCH + m];
        s += v; s2 += v*v;
    }
    r1[tid] = s; r2[tid] = s2; __syncthreads();
    for (int o = 128; o; o >>= 1) {
        if (tid < o) { r1[tid] += r1[tid+o]; r2[tid] += r2[tid+o]; }
        __syncthreads();
    }
    if (tid == 0) {
        float mu  = r1[0] / (float)LL;
        float var = r2[0] / (float)LL - mu*mu;
        g_mean[bm] = mu;
        g_std[bm]  = sqrtf(var + EPSV);
    }
}

// ---------------- patch embed ----------------
__global__ void patch_kernel(const float* __restrict__ x, const float* __restrict__ Win,
                             const float* __restrict__ bin) {
    int bmn = blockIdx.x;
    int bm = bmn >> 6, n = bmn & 63;
    int b = bm / MMCH, m = bm % MMCH;
    __shared__ float patch[PP];
    int tid = threadIdx.x;
    if (tid < PP) {
        int l = n*SSTR + tid;
        if (l > LL-1) l = LL-1;
        patch[tid] = (x[((size_t)b*LL + l)*MMCH + m] - g_mean[bm]) / g_std[bm];
    }
    __syncthreads();
    for (int d = tid; d < DD; d += 256) {
        float acc = bin[d];
        const float* wr = Win + (size_t)d*PP;
        #pragma unroll
        for (int p = 0; p < PP; p++) acc += patch[p]*wr[p];
        g_h[(size_t)bmn*DD + d] = acc;
    }
}

// ---------------- RMSNorm (fp16 out) ----------------
__global__ void rmsnorm_kernel(const float* __restrict__ in, const float* __restrict__ w,
                               __half* __restrict__ out) {
    __shared__ float red[256];
    int row = blockIdx.x, tid = threadIdx.x;
    const float* r = in + (size_t)row*DD;
    float s = 0.f;
    for (int i = tid; i < DD; i += 256) { float v = r[i]; s += v*v; }
    red[tid] = s; __syncthreads();
    for (int o = 128; o; o >>= 1) { if (tid < o) red[tid] += red[tid+o]; __syncthreads(); }
    float scale = rsqrtf(red[0]/(float)DD + EPSV);
    __half* outr = out + (size_t)row*DD;
    for (int i = tid; i < DD; i += 256) outr[i] = __float2half_rn(r[i]*scale*w[i]);
}

// ---------------- RoPE (on packed qkv) ----------------
__global__ void rope_kernel() {
    int row = blockIdx.x;
    int n = row & 63;
    float* base_q = g_qkv + (size_t)row*QKVN;
    float* base_k = base_q + 4096;
    int tid = threadIdx.x;
    const int qpairs = HHE*64;
    const int kpairs = KVH*64;
    for (int i = tid; i < qpairs + kpairs; i += 256) {
        float* base; int hh, d;
        if (i < qpairs) { base = base_q; hh = i >> 6; d = i & 63; }
        else            { int j = i - qpairs; base = base_k; hh = j >> 6; d = j & 63; }
        float f = powf(500000.0f, -(float)(2*d) / 128.0f);
        float a = (float)n * f;
        float c = cosf(a), s = sinf(a);
        float t0 = base[hh*HDIM + d];
        float t1 = base[hh*HDIM + d + 64];
        base[hh*HDIM + d]      = t0*c - t1*s;
        base[hh*HDIM + d + 64] = t1*c + t0*s;
    }
}

// ---------------- attention (packed qkv in, fp16 out) ----------------
__global__ void attn_kernel() {
    extern __shared__ float sm[];
    float* Qs = sm;
    float* Ks = Qs + 64*128;
    float* Vs = Ks + 128*65;
    float* Ss = Vs + 64*128;
    int bm = blockIdx.x, h = blockIdx.y, kvh = h >> 2;
    int tid = threadIdx.x;
    for (int i = tid; i < 64*128; i += 256) {
        int n = i >> 7, d = i & 127;
        size_t base = (size_t)(bm*64 + n)*QKVN;
        Qs[i] = g_qkv[base + h*HDIM + d];
        Ks[d*65 + n] = g_qkv[base + 4096 + kvh*HDIM + d];
        Vs[i] = g_qkv[base + 5120 + kvh*HDIM + d];
    }
    __syncthreads();
    const float scale = 0.08838834764831845f;
    for (int i = tid; i < 64*64; i += 256) {
        int qi = i >> 6, ki = i & 63;
        float acc;
        if (ki <= qi) {
            acc = 0.f;
            #pragma unroll 8
            for (int d = 0; d < 128; d++) acc += Qs[qi*128 + d]*Ks[d*65 + ki];
            acc *= scale;
        } else acc = -1e9f;
        Ss[qi*65 + ki] = acc;
    }
    __syncthreads();
    if (tid < 64) {
        float mx = -1e30f;
        for (int k = 0; k < 64; k++) mx = fmaxf(mx, Ss[tid*65 + k]);
        float sum = 0.f;
        for (int k = 0; k < 64; k++) { float e = expf(Ss[tid*65 + k] - mx); Ss[tid*65 + k] = e; sum += e; }
        float inv = 1.f / sum;
        for (int k = 0; k < 64; k++) Ss[tid*65 + k] *= inv;
    }
    __syncthreads();
    for (int i = tid; i < 64*128; i += 256) {
        int qi = i >> 7, d = i & 127;
        float acc = 0.f;
        #pragma unroll 8
        for (int k = 0; k < 64; k++) acc += Ss[qi*65 + k]*Vs[k*128 + d];
        g_o[(size_t)(bm*64 + qi)*DD + h*HDIM + d] = __float2half_rn(acc);
    }
}

// ---------------- FC reduce + head ----------------
__global__ void zreduce_kernel(const float* __restrict__ bfc) {
    int idx = blockIdx.x*256 + threadIdx.x;
    if (idx >= BMSEQ*FCN) return;
    int f = idx & 127, bm = idx >> 7;
    float acc = bfc[f];
    for (int ks = 0; ks < FCSPLIT; ks++) acc += g_zpart[(size_t)ks*16384 + bm*128 + f];
    g_z[idx] = acc;
}

__global__ void head_kernel(const float* __restrict__ Wout, const float* __restrict__ bout,
                            float* __restrict__ out) {
    __shared__ float zr[FCN];
    int bm = blockIdx.x, tid = threadIdx.x;
    if (tid < FCN) {
        float v = g_z[bm*FCN + tid];
        zr[tid] = v > 0.f ? v : 0.01f*v;
    }
    __syncthreads();
    if (tid < PREDN) {
        float acc = bout[tid];
        const float* wr = Wout + (size_t)tid*FCN;
        #pragma unroll 8
        for (int f = 0; f < FCN; f++) acc += zr[f]*wr[f];
        int b = bm / MMCH, m = bm % MMCH;
        out[(size_t)b*(PREDN*MMCH) + tid*MMCH + m] = acc*g_std[bm] + g_mean[bm];
    }
}

// ---------------- host ----------------
extern "C" void kernel_launch(void* const* d_in, const int* in_sizes, int n_in,
                              void* d_out, int out_size) {
    const float* x      = (const float*)d_in[0];
    const float* W_in   = (const float*)d_in[1];
    const float* b_in   = (const float*)d_in[2];
    const float* attn_w = (const float*)d_in[3];
    const float* Wq     = (const float*)d_in[4];
    const float* Wk     = (const float*)d_in[5];
    const float* Wv     = (const float*)d_in[6];
    const float* Wo     = (const float*)d_in[7];
    const float* mlp_w  = (const float*)d_in[8];
    const float* Wg     = (const float*)d_in[9];
    const float* Wu     = (const float*)d_in[10];
    const float* Wd     = (const float*)d_in[11];
    const float* fin_w  = (const float*)d_in[12];
    const float* W_fc   = (const float*)d_in[13];
    const float* b_fc   = (const float*)d_in[14];
    const float* W_out  = (const float*)d_in[15];
    const float* b_out  = (const float*)d_in[16];
    float* out = (float*)d_out;

    float *ph, *pqkv, *pzp;
    __half *phn, *po, *pg, *pu, *pw;
    cudaGetSymbolAddress((void**)&ph,   g_h);
    cudaGetSymbolAddress((void**)&phn,  g_hn);
    cudaGetSymbolAddress((void**)&pqkv, g_qkv);
    cudaGetSymbolAddress((void**)&po,   g_o);
    cudaGetSymbolAddress((void**)&pg,   g_gate);
    cudaGetSymbolAddress((void**)&pu,   g_up);
    cudaGetSymbolAddress((void**)&pzp,  g_zpart);
    cudaGetSymbolAddress((void**)&pw,   g_wtf);

    const int attn_smem = (64*128 + 128*65 + 64*128 + 64*65) * (int)sizeof(float);
    cudaFuncSetAttribute(attn_kernel, cudaFuncAttributeMaxDynamicSharedMemorySize, attn_smem);
    const int gsmem = NSTG * STAGEB;   // 81920
    cudaFuncSetAttribute(hgemm<0>, cudaFuncAttributeMaxDynamicSharedMemorySize, gsmem);
    cudaFuncSetAttribute(hgemm<1>, cudaFuncAttributeMaxDynamicSharedMemorySize, gsmem);
    cudaFuncSetAttribute(hgemm<2>, cudaFuncAttributeMaxDynamicSharedMemorySize, gsmem);
    cudaFuncSetAttribute(hgemm<3>, cudaFuncAttributeMaxDynamicSharedMemorySize, gsmem);

    // launch 0-1: weight fp16 convert (2 kernels; QKVO then GUD+FC)
    cvtw_a<<<(10485760 + 255)/256, 256>>>((const float4*)Wq, (const float4*)Wk,
                                          (const float4*)Wv, (const float4*)Wo);
    cvtw_b<<<(52428800 + 255)/256, 256>>>((const float4*)Wg, (const float4*)Wu,
                                          (const float4*)Wd, (const float4*)W_fc);
    const __half* tWqkv = pw + WOFF_Q;
    const __half* tWo = pw + WOFF_O;
    const __half* tWg = pw + WOFF_G;  const __half* tWu = pw + WOFF_U;
    const __half* tWd = pw + WOFF_D;  const __half* tWfc = pw + WOFF_FC;

    // launch 2: RevIN stats
    instnorm_kernel<<<BMSEQ, 256>>>(x);
    // launch 3: patch embed
    patch_kernel<<<TOK, 256>>>(x, W_in, b_in);
    // launch 4: attn RMSNorm -> fp16
    rmsnorm_kernel<<<TOK, 256>>>(ph, attn_w, phn);
    // launch 5 (ncu capture target): fused QKV projection (N=6144)
    {
        dim3 g(56*(QKVN/128), 1);
        hgemm<0><<<g, 256, gsmem>>>(phn, DD, tWqkv, DD, pqkv, QKVN, nullptr,
                                    56, QKVN/128, TOK, DD/32, 0, 0, 0);
    }
    // RoPE
    rope_kernel<<<TOK, 256>>>();
    // attention -> fp16 o
    {
        dim3 grid(BMSEQ, HHE);
        attn_kernel<<<grid, 256, attn_smem>>>();
    }
    // output proj + residual
    {
        dim3 g(56*32, 1);
        hgemm<1><<<g, 256, gsmem>>>(po, DD, tWo, DD, ph, DD, ph,
                                    56, 32, TOK, DD/32, 0, 0, 0);
    }
    // mlp RMSNorm -> fp16
    rmsnorm_kernel<<<TOK, 256>>>(ph, mlp_w, phn);
    // up proj (fp16 out), gate proj fused silu*up (fp16 aux, fp16 out)
    {
        dim3 g(56*112, 1);
        hgemm<3><<<g, 256, gsmem>>>(phn, DD, tWu, DD, pu, DFFN, nullptr,
                                    56, 112, TOK, DD/32, 0, 0, 0);
        hgemm<2><<<g, 256, gsmem>>>(phn, DD, tWg, DD, pg, DFFN, pu,
                                    56, 112, TOK, DD/32, 0, 0, 0);
    }
    // down proj + residual
    {
        dim3 g(56*32, 1);
        hgemm<1><<<g, 256, gsmem>>>(pg, DFFN, tWd, DFFN, ph, DD, ph,
                                    56, 32, TOK, DFFN/32, 0, 0, 0);
    }
    // final RMSNorm -> fp16
    rmsnorm_kernel<<<TOK, 256>>>(ph, fin_w, phn);
    // FC head: split-K fp16 GEMM (128 splits)
    {
        dim3 g(1, FCSPLIT);
        hgemm<0><<<g, 256, gsmem>>>(phn, KFC, tWfc, KFC, pzp, 128, nullptr,
                                    1, 1, 112, (KFC/FCSPLIT)/32,
                                    KFC/FCSPLIT, KFC/FCSPLIT, 128*128);
    }
    // reduce + head
    zreduce_kernel<<<(BMSEQ*FCN + 255)/256, 256>>>(b_fc);
    head_kernel<<<BMSEQ, 128>>>(W_out, b_out, out);
}

// round 15
// speedup vs baseline: 1.4359x; 1.0487x over previous
#include <cuda_runtime.h>
#include <cuda_fp16.h>
#include <math.h>
#include <stdint.h>

// ---------------- problem constants ----------------
#define BB   16
#define LL   512
#define MMCH 7
#define PP   16
#define SSTR 8
#define NPAT 64
#define DD   4096
#define HHE  32
#define KVH  8
#define HDIM 128
#define DFFN 14336
#define FCN  128
#define PREDN 96
#define BMSEQ (BB*MMCH)        // 112
#define TOK   (BMSEQ*NPAT)     // 7168
#define KFC   (NPAT*DD)        // 262144
#define QKVN  6144
#define FCSPLIT 128
#define EPSV 1e-5f

// ---------------- scratch ----------------
__device__ float g_mean[BMSEQ];
__device__ float g_std[BMSEQ];
__device__ float g_h [(size_t)TOK*DD];
__device__ __half g_hn[(size_t)TOK*DD];
__device__ float g_qkv[(size_t)TOK*QKVN];
__device__ __half g_o [(size_t)TOK*DD];
__device__ __half g_gate[(size_t)TOK*DFFN];
__device__ __half g_up  [(size_t)TOK*DFFN];
__device__ float g_zpart[(size_t)FCSPLIT*128*128];
__device__ float g_z[BMSEQ*FCN];
// fp16 weights (0.5 GB); Q,K,V contiguous -> fused QKV GEMM
#define WOFF_Q  0
#define WOFF_K  16777216
#define WOFF_V  20971520
#define WOFF_O  25165824
#define WOFF_G  41943040
#define WOFF_U  100663296
#define WOFF_D  159383552
#define WOFF_FC 218103808
#define WTF_TOTAL 251658240
__device__ __half g_wtf[(size_t)WTF_TOTAL];

__device__ __forceinline__ uint32_t smem_u32(const void* p) {
    uint32_t a;
    asm("{ .reg .u64 t; cvta.to.shared.u64 t, %1; cvt.u32.u64 %0, t; }" : "=r"(a) : "l"(p));
    return a;
}
__device__ __forceinline__ void mma_f16(float c[4], const uint32_t a[4], const uint32_t b[2]) {
    asm volatile("mma.sync.aligned.m16n8k16.row.col.f32.f16.f16.f32 "
        "{%0,%1,%2,%3}, {%4,%5,%6,%7}, {%8,%9}, {%0,%1,%2,%3};"
        : "+f"(c[0]), "+f"(c[1]), "+f"(c[2]), "+f"(c[3])
        : "r"(a[0]), "r"(a[1]), "r"(a[2]), "r"(a[3]), "r"(b[0]), "r"(b[1]));
}
#define LDSM_X4(r0,r1,r2,r3,addr) \
    asm volatile("ldmatrix.sync.aligned.m8n8.x4.shared.b16 {%0,%1,%2,%3}, [%4];" \
        : "=r"(r0), "=r"(r1), "=r"(r2), "=r"(r3) : "r"(addr))
#define CP_ASYNC16(dst, src) \
    asm volatile("cp.async.cg.shared.global [%0], [%1], 16;" :: "r"(dst), "l"(src) : "memory")
#define CP_COMMIT() asm volatile("cp.async.commit_group;" ::: "memory")
#define CP_WAIT2()  asm volatile("cp.async.wait_group 2;" ::: "memory")

// ---------------- weight fp16 convert (2 launches) ----------------
__device__ __forceinline__ void cvt_store(__half2* dst, int i, float4 v) {
    dst[2*i]   = __floats2half2_rn(v.x, v.y);
    dst[2*i+1] = __floats2half2_rn(v.z, v.w);
}
__global__ void cvtw_a(const float4* __restrict__ q, const float4* __restrict__ k,
                       const float4* __restrict__ v, const float4* __restrict__ o) {
    int i = blockIdx.x*256 + threadIdx.x;
    __half2* dst = (__half2*)g_wtf;
    if      (i <  4194304) cvt_store(dst, i, q[i]);
    else if (i <  5242880) cvt_store(dst, i, k[i - 4194304]);
    else if (i <  6291456) cvt_store(dst, i, v[i - 5242880]);
    else if (i < 10485760) cvt_store(dst, i, o[i - 6291456]);
}
__global__ void cvtw_b(const float4* __restrict__ g, const float4* __restrict__ u,
                       const float4* __restrict__ d, const float4* __restrict__ fc) {
    int i = blockIdx.x*256 + threadIdx.x;
    __half2* dst = (__half2*)(g_wtf + WOFF_G);
    if      (i < 14680064) cvt_store(dst, i, g[i]);
    else if (i < 29360128) cvt_store(dst, i, u[i - 14680064]);
    else if (i < 44040192) cvt_store(dst, i, d[i - 29360128]);
    else if (i < 52428800) cvt_store(dst, i, fc[i - 44040192]);
}

// ---------------- fp16 mma GEMM: ldmatrix + cp.async 4-stage ----------------
#define KSH 40
#define TILEA_H (128*KSH)
#define STAGE_H (256*KSH)
#define STAGEB  (STAGE_H*2)
#define NSTG 4

template<int MODE>
__global__ void __launch_bounds__(256, 2)
hgemm(const __half* __restrict__ A, int lda,
      const __half* __restrict__ W, int ldw,
      void* __restrict__ Cv, int ldc,
      const void* __restrict__ aux,
      int Mtiles, int Ntiles, int Mvalid, int kchunks,
      long ksA, long ksW, long ksC)
{
    extern __shared__ __align__(16) __half smh[];
    const uint32_t sb_u = smem_u32(smh);
    const int tid = threadIdx.x;

    A += (size_t)blockIdx.y * ksA;
    W += (size_t)blockIdx.y * ksW;

    int mt, nt;
    {
        const int GM = 16;
        int perg = GM * Ntiles;
        int g = blockIdx.x / perg, rem = blockIdx.x % perg;
        int gm = Mtiles - g*GM; if (gm > GM) gm = GM;
        mt = g*GM + rem % gm;
        nt = rem / gm;
    }

    const __half* gsrc;
    uint32_t srow;
    if (tid < 128) {
        int gr = mt*128 + tid; if (gr >= Mvalid) gr = Mvalid-1;
        gsrc = A + (size_t)gr*lda;
        srow = (uint32_t)tid*(KSH*2);
    } else {
        gsrc = W + (size_t)(nt*128 + (tid-128))*ldw;
        srow = (uint32_t)(TILEA_H*2) + (uint32_t)(tid-128)*(KSH*2);
    }

    const int warp = tid >> 5, lane = tid & 31;
    const int wm = warp & 3, wn = warp >> 2;
    const int gid = lane >> 2, quad = lane & 3;

    uint32_t aAddr[2], bAddr[4];
    #pragma unroll
    for (int f = 0; f < 2; f++)
        aAddr[f] = sb_u + (uint32_t)(((wm*32 + f*16 + (lane & 15))*KSH + (lane >> 4)*8) * 2);
    #pragma unroll
    for (int p = 0; p < 4; p++)
        bAddr[p] = sb_u + (uint32_t)((TILEA_H + (wn*64 + p*16 + (lane & 7) + ((lane >> 4) << 3))*KSH
                                      + ((lane >> 3) & 1)*8) * 2);

    float acc[2][8][4];
    #pragma unroll
    for (int f = 0; f < 2; f++)
        #pragma unroll
        for (int g = 0; g < 8; g++)
            #pragma unroll
            for (int j = 0; j < 4; j++) acc[f][g][j] = 0.f;

    #pragma unroll
    for (int s = 0; s < 3; s++) {
        uint32_t base = sb_u + (uint32_t)s*STAGEB + srow;
        #pragma unroll
        for (int i = 0; i < 4; i++) CP_ASYNC16(base + i*16, gsrc + s*32 + i*8);
        CP_COMMIT();
    }

    int st = 0;
    for (int kc = 0; kc < kchunks; kc++) {
        CP_WAIT2();
        __syncthreads();
        if (kc + 3 < kchunks) {
            int s3 = st + 3; if (s3 >= NSTG) s3 -= NSTG;
            uint32_t base = sb_u + (uint32_t)s3*STAGEB + srow;
            const __half* gk = gsrc + (size_t)(kc+3)*32;
            #pragma unroll
            for (int i = 0; i < 4; i++) CP_ASYNC16(base + i*16, gk + i*8);
        }
        CP_COMMIT();
        const uint32_t stOff = (uint32_t)st*STAGEB;
        #pragma unroll
        for (int ks = 0; ks < 2; ks++) {
            const uint32_t koff = stOff + ks*32;
            uint32_t a[2][4];
            LDSM_X4(a[0][0], a[0][1], a[0][2], a[0][3], aAddr[0] + koff);
            LDSM_X4(a[1][0], a[1][1], a[1][2], a[1][3], aAddr[1] + koff);
            uint32_t b[8][2];
            #pragma unroll
            for (int p = 0; p < 4; p++)
                LDSM_X4(b[2*p][0], b[2*p][1], b[2*p+1][0], b[2*p+1][1], bAddr[p] + koff);
            #pragma unroll
            for (int f = 0; f < 2; f++)
                #pragma unroll
                for (int g = 0; g < 8; g++)
                    mma_f16(acc[f][g], a[f], b[g]);
        }
        st = st + 1; if (st == NSTG) st = 0;
    }

    #pragma unroll
    for (int f = 0; f < 2; f++) {
        int r0 = mt*128 + wm*32 + f*16 + gid;
        #pragma unroll
        for (int g = 0; g < 8; g++) {
            int col = nt*128 + wn*64 + g*8 + 2*quad;
            #pragma unroll
            for (int half_ = 0; half_ < 2; half_++) {
                int row = r0 + half_*8;
                if (row >= Mvalid) continue;
                float v0 = acc[f][g][half_*2 + 0];
                float v1 = acc[f][g][half_*2 + 1];
                size_t off = (size_t)row*ldc + col;
                if (MODE == 2) {
                    __half2 uh = *(const __half2*)((const __half*)aux + off);
                    float2 uf = __half22float2(uh);
                    v0 = v0 / (1.f + __expf(-v0)) * uf.x;
                    v1 = v1 / (1.f + __expf(-v1)) * uf.y;
                    *(__half2*)((__half*)Cv + off) = __floats2half2_rn(v0, v1);
                } else if (MODE == 3) {
                    *(__half2*)((__half*)Cv + off) = __floats2half2_rn(v0, v1);
                } else {
                    if (MODE == 1) {
                        const float* ax = (const float*)aux;
                        v0 += ax[off]; v1 += ax[off+1];
                    }
                    float* C = (float*)Cv + (size_t)blockIdx.y*ksC;
                    float2 o; o.x = v0; o.y = v1;
                    *(float2*)(C + off) = o;
                }
            }
        }
    }
}

// ---------------- instance norm ----------------
__global__ void instnorm_kernel(const float* __restrict__ x) {
    __shared__ float r1[256], r2[256];
    int bm = blockIdx.x, b = bm / MMCH, m = bm % MMCH, tid = threadIdx.x;
    float s = 0.f, s2 = 0.f;
    for (int l = tid; l < LL; l += 256) {
        float v = x[((size_t)b*LL + l)*MMCH + m];
        s += v; s2 += v*v;
    }
    r1[tid] = s; r2[tid] = s2; __syncthreads();
    for (int o = 128; o; o >>= 1) {
        if (tid < o) { r1[tid] += r1[tid+o]; r2[tid] += r2[tid+o]; }
        __syncthreads();
    }
    if (tid == 0) {
        float mu  = r1[0] / (float)LL;
        float var = r2[0] / (float)LL - mu*mu;
        g_mean[bm] = mu;
        g_std[bm]  = sqrtf(var + EPSV);
    }
}

// ---------------- patch embed: per-sequence blocks, W_in staged through SMEM ----------------
// 112 blocks; each computes h[bm*64 .. bm*64+63][0..4095].
__global__ void __launch_bounds__(256)
patch_kernel(const float* __restrict__ x, const float* __restrict__ Win,
             const float* __restrict__ bin) {
    __shared__ float ps[NPAT*17];    // patches [64][16] padded
    __shared__ float ws[128*17];     // W_in chunk [128][16] padded
    int bm = blockIdx.x, b = bm / MMCH, m = bm % MMCH, tid = threadIdx.x;
    float mean = g_mean[bm], inv = 1.f / g_std[bm];
    // build patch matrix (replication-pad)
    for (int i = tid; i < NPAT*PP; i += 256) {
        int n = i >> 4, p = i & 15;
        int l = n*SSTR + p; if (l > LL-1) l = LL-1;
        ps[n*17 + p] = (x[((size_t)b*LL + l)*MMCH + m] - mean) * inv;
    }
    const int dloc = tid & 127, ngrp = tid >> 7;
    for (int dc = 0; dc < DD/128; dc++) {
        __syncthreads();   // ps ready / previous compute done before ws overwrite
        // load W_in chunk (contiguous 8KB, coalesced)
        for (int i = tid; i < 128*PP; i += 256) {
            int r = i >> 4, p = i & 15;
            ws[r*17 + p] = Win[(size_t)dc*128*PP + i];
        }
        __syncthreads();
        float w[16];
        #pragma unroll
        for (int p = 0; p < 16; p++) w[p] = ws[dloc*17 + p];
        float bv = bin[dc*128 + dloc];
        #pragma unroll 4
        for (int n0 = 0; n0 < 32; n0++) {
            int n = ngrp*32 + n0;
            float acc = bv;
            #pragma unroll
            for (int p = 0; p < 16; p++) acc += ps[n*17 + p] * w[p];
            g_h[((size_t)(bm*NPAT + n))*DD + dc*128 + dloc] = acc;
        }
    }
}

// ---------------- RMSNorm (fp16 out) ----------------
__global__ void rmsnorm_kernel(const float* __restrict__ in, const float* __restrict__ w,
                               __half* __restrict__ out) {
    __shared__ float red[256];
    int row = blockIdx.x, tid = threadIdx.x;
    const float* r = in + (size_t)row*DD;
    float s = 0.f;
    for (int i = tid; i < DD; i += 256) { float v = r[i]; s += v*v; }
    red[tid] = s; __syncthreads();
    for (int o = 128; o; o >>= 1) { if (tid < o) red[tid] += red[tid+o]; __syncthreads(); }
    float scale = rsqrtf(red[0]/(float)DD + EPSV);
    __half* outr = out + (size_t)row*DD;
    for (int i = tid; i < DD; i += 256) outr[i] = __float2half_rn(r[i]*scale*w[i]);
}

// ---------------- RoPE (on packed qkv; fast transcendentals) ----------------
#define ROPE_L2C 0.29580585549875576f   // log2(500000)/64
__global__ void rope_kernel() {
    int row = blockIdx.x;
    int n = row & 63;
    float* base_q = g_qkv + (size_t)row*QKVN;
    float* base_k = base_q + 4096;
    int tid = threadIdx.x;
    const int qpairs = HHE*64;
    const int kpairs = KVH*64;
    for (int i = tid; i < qpairs + kpairs; i += 256) {
        float* base; int hh, d;
        if (i < qpairs) { base = base_q; hh = i >> 6; d = i & 63; }
        else            { int j = i - qpairs; base = base_k; hh = j >> 6; d = j & 63; }
        float f = exp2f(-ROPE_L2C * (float)d);
        float a = (float)n * f;
        float c, s;
        __sincosf(a, &s, &c);
        float t0 = base[hh*HDIM + d];
        float t1 = base[hh*HDIM + d + 64];
        base[hh*HDIM + d]      = t0*c - t1*s;
        base[hh*HDIM + d + 64] = t1*c + t0*s;
    }
}

// ---------------- attention (packed qkv in, fp16 out) ----------------
__global__ void attn_kernel() {
    extern __shared__ float sm[];
    float* Qs = sm;
    float* Ks = Qs + 64*128;
    float* Vs = Ks + 128*65;
    float* Ss = Vs + 64*128;
    int bm = blockIdx.x, h = blockIdx.y, kvh = h >> 2;
    int tid = threadIdx.x;
    for (int i = tid; i < 64*128; i += 256) {
        int n = i >> 7, d = i & 127;
        size_t base = (size_t)(bm*64 + n)*QKVN;
        Qs[i] = g_qkv[base + h*HDIM + d];
        Ks[d*65 + n] = g_qkv[base + 4096 + kvh*HDIM + d];
        Vs[i] = g_qkv[base + 5120 + kvh*HDIM + d];
    }
    __syncthreads();
    const float scale = 0.08838834764831845f;
    for (int i = tid; i < 64*64; i += 256) {
        int qi = i >> 6, ki = i & 63;
        float acc;
        if (ki <= qi) {
            acc = 0.f;
            #pragma unroll 8
            for (int d = 0; d < 128; d++) acc += Qs[qi*128 + d]*Ks[d*65 + ki];
            acc *= scale;
        } else acc = -1e9f;
        Ss[qi*65 + ki] = acc;
    }
    __syncthreads();
    if (tid < 64) {
        float mx = -1e30f;
        for (int k = 0; k < 64; k++) mx = fmaxf(mx, Ss[tid*65 + k]);
        float sum = 0.f;
        for (int k = 0; k < 64; k++) { float e = __expf(Ss[tid*65 + k] - mx); Ss[tid*65 + k] = e; sum += e; }
        float inv = 1.f / sum;
        for (int k = 0; k < 64; k++) Ss[tid*65 + k] *= inv;
    }
    __syncthreads();
    for (int i = tid; i < 64*128; i += 256) {
        int qi = i >> 7, d = i & 127;
        float acc = 0.f;
        #pragma unroll 8
        for (int k = 0; k < 64; k++) acc += Ss[qi*65 + k]*Vs[k*128 + d];
        g_o[(size_t)(bm*64 + qi)*DD + h*HDIM + d] = __float2half_rn(acc);
    }
}

// ---------------- FC reduce + head ----------------
__global__ void zreduce_kernel(const float* __restrict__ bfc) {
    int idx = blockIdx.x*256 + threadIdx.x;
    if (idx >= BMSEQ*FCN) return;
    int f = idx & 127, bm = idx >> 7;
    float acc = bfc[f];
    for (int ks = 0; ks < FCSPLIT; ks++) acc += g_zpart[(size_t)ks*16384 + bm*128 + f];
    g_z[idx] = acc;
}

__global__ void head_kernel(const float* __restrict__ Wout, const float* __restrict__ bout,
                            float* __restrict__ out) {
    __shared__ float zr[FCN];
    int bm = blockIdx.x, tid = threadIdx.x;
    if (tid < FCN) {
        float v = g_z[bm*FCN + tid];
        zr[tid] = v > 0.f ? v : 0.01f*v;
    }
    __syncthreads();
    if (tid < PREDN) {
        float acc = bout[tid];
        const float* wr = Wout + (size_t)tid*FCN;
        #pragma unroll 8
        for (int f = 0; f < FCN; f++) acc += zr[f]*wr[f];
        int b = bm / MMCH, m = bm % MMCH;
        out[(size_t)b*(PREDN*MMCH) + tid*MMCH + m] = acc*g_std[bm] + g_mean[bm];
    }
}

// ---------------- host ----------------
extern "C" void kernel_launch(void* const* d_in, const int* in_sizes, int n_in,
                              void* d_out, int out_size) {
    const float* x      = (const float*)d_in[0];
    const float* W_in   = (const float*)d_in[1];
    const float* b_in   = (const float*)d_in[2];
    const float* attn_w = (const float*)d_in[3];
    const float* Wq     = (const float*)d_in[4];
    const float* Wk     = (const float*)d_in[5];
    const float* Wv     = (const float*)d_in[6];
    const float* Wo     = (const float*)d_in[7];
    const float* mlp_w  = (const float*)d_in[8];
    const float* Wg     = (const float*)d_in[9];
    const float* Wu     = (const float*)d_in[10];
    const float* Wd     = (const float*)d_in[11];
    const float* fin_w  = (const float*)d_in[12];
    const float* W_fc   = (const float*)d_in[13];
    const float* b_fc   = (const float*)d_in[14];
    const float* W_out  = (const float*)d_in[15];
    const float* b_out  = (const float*)d_in[16];
    float* out = (float*)d_out;

    float *ph, *pqkv, *pzp;
    __half *phn, *po, *pg, *pu, *pw;
    cudaGetSymbolAddress((void**)&ph,   g_h);
    cudaGetSymbolAddress((void**)&phn,  g_hn);
    cudaGetSymbolAddress((void**)&pqkv, g_qkv);
    cudaGetSymbolAddress((void**)&po,   g_o);
    cudaGetSymbolAddress((void**)&pg,   g_gate);
    cudaGetSymbolAddress((void**)&pu,   g_up);
    cudaGetSymbolAddress((void**)&pzp,  g_zpart);
    cudaGetSymbolAddress((void**)&pw,   g_wtf);

    const int attn_smem = (64*128 + 128*65 + 64*128 + 64*65) * (int)sizeof(float);
    cudaFuncSetAttribute(attn_kernel, cudaFuncAttributeMaxDynamicSharedMemorySize, attn_smem);
    const int gsmem = NSTG * STAGEB;   // 81920
    cudaFuncSetAttribute(hgemm<0>, cudaFuncAttributeMaxDynamicSharedMemorySize, gsmem);
    cudaFuncSetAttribute(hgemm<1>, cudaFuncAttributeMaxDynamicSharedMemorySize, gsmem);
    cudaFuncSetAttribute(hgemm<2>, cudaFuncAttributeMaxDynamicSharedMemorySize, gsmem);
    cudaFuncSetAttribute(hgemm<3>, cudaFuncAttributeMaxDynamicSharedMemorySize, gsmem);

    // launch 0-1: weight fp16 convert
    cvtw_a<<<(10485760 + 255)/256, 256>>>((const float4*)Wq, (const float4*)Wk,
                                          (const float4*)Wv, (const float4*)Wo);
    cvtw_b<<<(52428800 + 255)/256, 256>>>((const float4*)Wg, (const float4*)Wu,
                                          (const float4*)Wd, (const float4*)W_fc);
    const __half* tWqkv = pw + WOFF_Q;
    const __half* tWo = pw + WOFF_O;
    const __half* tWg = pw + WOFF_G;  const __half* tWu = pw + WOFF_U;
    const __half* tWd = pw + WOFF_D;  const __half* tWfc = pw + WOFF_FC;

    // launch 2: RevIN stats
    instnorm_kernel<<<BMSEQ, 256>>>(x);
    // launch 3: patch embed (112 blocks, SMEM-staged W_in)
    patch_kernel<<<BMSEQ, 256>>>(x, W_in, b_in);
    // launch 4: attn RMSNorm -> fp16
    rmsnorm_kernel<<<TOK, 256>>>(ph, attn_w, phn);
    // launch 5: fused QKV projection (N=6144)
    {
        dim3 g(56*(QKVN/128), 1);
        hgemm<0><<<g, 256, gsmem>>>(phn, DD, tWqkv, DD, pqkv, QKVN, nullptr,
                                    56, QKVN/128, TOK, DD/32, 0, 0, 0);
    }
    // RoPE
    rope_kernel<<<TOK, 256>>>();
    // attention -> fp16 o
    {
        dim3 grid(BMSEQ, HHE);
        attn_kernel<<<grid, 256, attn_smem>>>();
    }
    // output proj + residual
    {
        dim3 g(56*32, 1);
        hgemm<1><<<g, 256, gsmem>>>(po, DD, tWo, DD, ph, DD, ph,
                                    56, 32, TOK, DD/32, 0, 0, 0);
    }
    // mlp RMSNorm -> fp16
    rmsnorm_kernel<<<TOK, 256>>>(ph, mlp_w, phn);
    // up proj (fp16 out), gate proj fused silu*up
    {
        dim3 g(56*112, 1);
        hgemm<3><<<g, 256, gsmem>>>(phn, DD, tWu, DD, pu, DFFN, nullptr,
                                    56, 112, TOK, DD/32, 0, 0, 0);
        hgemm<2><<<g, 256, gsmem>>>(phn, DD, tWg, DD, pg, DFFN, pu,
                                    56, 112, TOK, DD/32, 0, 0, 0);
    }
    // down proj + residual
    {
        dim3 g(56*32, 1);
        hgemm<1><<<g, 256, gsmem>>>(pg, DFFN, tWd, DFFN, ph, DD, ph,
                                    56, 32, TOK, DFFN/32, 0, 0, 0);
    }
    // final RMSNorm -> fp16
    rmsnorm_kernel<<<TOK, 256>>>(ph, fin_w, phn);
    // FC head: split-K fp16 GEMM (128 splits)
    {
        dim3 g(1, FCSPLIT);
        hgemm<0><<<g, 256, gsmem>>>(phn, KFC, tWfc, KFC, pzp, 128, nullptr,
                                    1, 1, 112, (KFC/FCSPLIT)/32,
                                    KFC/FCSPLIT, KFC/FCSPLIT, 128*128);
    }
    // reduce + head
    zreduce_kernel<<<(BMSEQ*FCN + 255)/256, 256>>>(b_fc);
    head_kernel<<<BMSEQ, 128>>>(W_out, b_out, out);
}

// round 16
// speedup vs baseline: 1.4424x; 1.0045x over previous
#include <cuda_runtime.h>
#include <cuda_fp16.h>
#include <math.h>
#include <stdint.h>

// ---------------- problem constants ----------------
#define BB   16
#define LL   512
#define MMCH 7
#define PP   16
#define SSTR 8
#define NPAT 64
#define DD   4096
#define HHE  32
#define KVH  8
#define HDIM 128
#define DFFN 14336
#define FCN  128
#define PREDN 96
#define BMSEQ (BB*MMCH)        // 112
#define TOK   (BMSEQ*NPAT)     // 7168
#define KFC   (NPAT*DD)        // 262144
#define QKVN  6144
#define FCSPLIT 128
#define EPSV 1e-5f

// ---------------- scratch ----------------
__device__ float g_mean[BMSEQ];
__device__ float g_std[BMSEQ];
__device__ float g_h [(size_t)TOK*DD];
__device__ __half g_hn[(size_t)TOK*DD];
__device__ __half g_qkv[(size_t)TOK*QKVN];
__device__ __half g_o [(size_t)TOK*DD];
__device__ __half g_gate[(size_t)TOK*DFFN];
__device__ __half g_up  [(size_t)TOK*DFFN];
__device__ float g_zpart[(size_t)FCSPLIT*128*128];
__device__ float g_z[BMSEQ*FCN];
// fp16 weights (0.5 GB); Q,K,V contiguous -> fused QKV GEMM
#define WOFF_Q  0
#define WOFF_K  16777216
#define WOFF_V  20971520
#define WOFF_O  25165824
#define WOFF_G  41943040
#define WOFF_U  100663296
#define WOFF_D  159383552
#define WOFF_FC 218103808
#define WTF_TOTAL 251658240
__device__ __half g_wtf[(size_t)WTF_TOTAL];

__device__ __forceinline__ uint32_t smem_u32(const void* p) {
    uint32_t a;
    asm("{ .reg .u64 t; cvta.to.shared.u64 t, %1; cvt.u32.u64 %0, t; }" : "=r"(a) : "l"(p));
    return a;
}
__device__ __forceinline__ void mma_f16(float c[4], const uint32_t a[4], const uint32_t b[2]) {
    asm volatile("mma.sync.aligned.m16n8k16.row.col.f32.f16.f16.f32 "
        "{%0,%1,%2,%3}, {%4,%5,%6,%7}, {%8,%9}, {%0,%1,%2,%3};"
        : "+f"(c[0]), "+f"(c[1]), "+f"(c[2]), "+f"(c[3])
        : "r"(a[0]), "r"(a[1]), "r"(a[2]), "r"(a[3]), "r"(b[0]), "r"(b[1]));
}
#define LDSM_X4(r0,r1,r2,r3,addr) \
    asm volatile("ldmatrix.sync.aligned.m8n8.x4.shared.b16 {%0,%1,%2,%3}, [%4];" \
        : "=r"(r0), "=r"(r1), "=r"(r2), "=r"(r3) : "r"(addr))
#define CP_ASYNC16(dst, src) \
    asm volatile("cp.async.cg.shared.global [%0], [%1], 16;" :: "r"(dst), "l"(src) : "memory")
#define CP_COMMIT() asm volatile("cp.async.commit_group;" ::: "memory")
#define CP_WAIT2()  asm volatile("cp.async.wait_group 2;" ::: "memory")

// ---------------- weight fp16 convert (2 launches) ----------------
__device__ __forceinline__ void cvt_store(__half2* dst, int i, float4 v) {
    dst[2*i]   = __floats2half2_rn(v.x, v.y);
    dst[2*i+1] = __floats2half2_rn(v.z, v.w);
}
__global__ void cvtw_a(const float4* __restrict__ q, const float4* __restrict__ k,
                       const float4* __restrict__ v, const float4* __restrict__ o) {
    int i = blockIdx.x*256 + threadIdx.x;
    __half2* dst = (__half2*)g_wtf;
    if      (i <  4194304) cvt_store(dst, i, q[i]);
    else if (i <  5242880) cvt_store(dst, i, k[i - 4194304]);
    else if (i <  6291456) cvt_store(dst, i, v[i - 5242880]);
    else if (i < 10485760) cvt_store(dst, i, o[i - 6291456]);
}
__global__ void cvtw_b(const float4* __restrict__ g, const float4* __restrict__ u,
                       const float4* __restrict__ d, const float4* __restrict__ fc) {
    int i = blockIdx.x*256 + threadIdx.x;
    __half2* dst = (__half2*)(g_wtf + WOFF_G);
    if      (i < 14680064) cvt_store(dst, i, g[i]);
    else if (i < 29360128) cvt_store(dst, i, u[i - 14680064]);
    else if (i < 44040192) cvt_store(dst, i, d[i - 29360128]);
    else if (i < 52428800) cvt_store(dst, i, fc[i - 44040192]);
}

// ---------------- fp16 mma GEMM: ldmatrix + cp.async 4-stage ----------------
#define KSH 40
#define TILEA_H (128*KSH)
#define STAGE_H (256*KSH)
#define STAGEB  (STAGE_H*2)
#define NSTG 4

template<int MODE>
__global__ void __launch_bounds__(256, 2)
hgemm(const __half* __restrict__ A, int lda,
      const __half* __restrict__ W, int ldw,
      void* __restrict__ Cv, int ldc,
      const void* __restrict__ aux,
      int Mtiles, int Ntiles, int Mvalid, int kchunks,
      long ksA, long ksW, long ksC)
{
    extern __shared__ __align__(16) __half smh[];
    const uint32_t sb_u = smem_u32(smh);
    const int tid = threadIdx.x;

    A += (size_t)blockIdx.y * ksA;
    W += (size_t)blockIdx.y * ksW;

    int mt, nt;
    {
        const int GM = 16;
        int perg = GM * Ntiles;
        int g = blockIdx.x / perg, rem = blockIdx.x % perg;
        int gm = Mtiles - g*GM; if (gm > GM) gm = GM;
        mt = g*GM + rem % gm;
        nt = rem / gm;
    }

    const __half* gsrc;
    uint32_t srow;
    if (tid < 128) {
        int gr = mt*128 + tid; if (gr >= Mvalid) gr = Mvalid-1;
        gsrc = A + (size_t)gr*lda;
        srow = (uint32_t)tid*(KSH*2);
    } else {
        gsrc = W + (size_t)(nt*128 + (tid-128))*ldw;
        srow = (uint32_t)(TILEA_H*2) + (uint32_t)(tid-128)*(KSH*2);
    }

    const int warp = tid >> 5, lane = tid & 31;
    const int wm = warp & 3, wn = warp >> 2;
    const int gid = lane >> 2, quad = lane & 3;

    uint32_t aAddr[2], bAddr[4];
    #pragma unroll
    for (int f = 0; f < 2; f++)
        aAddr[f] = sb_u + (uint32_t)(((wm*32 + f*16 + (lane & 15))*KSH + (lane >> 4)*8) * 2);
    #pragma unroll
    for (int p = 0; p < 4; p++)
        bAddr[p] = sb_u + (uint32_t)((TILEA_H + (wn*64 + p*16 + (lane & 7) + ((lane >> 4) << 3))*KSH
                                      + ((lane >> 3) & 1)*8) * 2);

    float acc[2][8][4];
    #pragma unroll
    for (int f = 0; f < 2; f++)
        #pragma unroll
        for (int g = 0; g < 8; g++)
            #pragma unroll
            for (int j = 0; j < 4; j++) acc[f][g][j] = 0.f;

    #pragma unroll
    for (int s = 0; s < 3; s++) {
        uint32_t base = sb_u + (uint32_t)s*STAGEB + srow;
        #pragma unroll
        for (int i = 0; i < 4; i++) CP_ASYNC16(base + i*16, gsrc + s*32 + i*8);
        CP_COMMIT();
    }

    int st = 0;
    for (int kc = 0; kc < kchunks; kc++) {
        CP_WAIT2();
        __syncthreads();
        if (kc + 3 < kchunks) {
            int s3 = st + 3; if (s3 >= NSTG) s3 -= NSTG;
            uint32_t base = sb_u + (uint32_t)s3*STAGEB + srow;
            const __half* gk = gsrc + (size_t)(kc+3)*32;
            #pragma unroll
            for (int i = 0; i < 4; i++) CP_ASYNC16(base + i*16, gk + i*8);
        }
        CP_COMMIT();
        const uint32_t stOff = (uint32_t)st*STAGEB;
        #pragma unroll
        for (int ks = 0; ks < 2; ks++) {
            const uint32_t koff = stOff + ks*32;
            uint32_t a[2][4];
            LDSM_X4(a[0][0], a[0][1], a[0][2], a[0][3], aAddr[0] + koff);
            LDSM_X4(a[1][0], a[1][1], a[1][2], a[1][3], aAddr[1] + koff);
            uint32_t b[8][2];
            #pragma unroll
            for (int p = 0; p < 4; p++)
                LDSM_X4(b[2*p][0], b[2*p][1], b[2*p+1][0], b[2*p+1][1], bAddr[p] + koff);
            #pragma unroll
            for (int f = 0; f < 2; f++)
                #pragma unroll
                for (int g = 0; g < 8; g++)
                    mma_f16(acc[f][g], a[f], b[g]);
        }
        st = st + 1; if (st == NSTG) st = 0;
    }

    #pragma unroll
    for (int f = 0; f < 2; f++) {
        int r0 = mt*128 + wm*32 + f*16 + gid;
        #pragma unroll
        for (int g = 0; g < 8; g++) {
            int col = nt*128 + wn*64 + g*8 + 2*quad;
            #pragma unroll
            for (int half_ = 0; half_ < 2; half_++) {
                int row = r0 + half_*8;
                if (row >= Mvalid) continue;
                float v0 = acc[f][g][half_*2 + 0];
                float v1 = acc[f][g][half_*2 + 1];
                size_t off = (size_t)row*ldc + col;
                if (MODE == 2) {
                    __half2 uh = *(const __half2*)((const __half*)aux + off);
                    float2 uf = __half22float2(uh);
                    v0 = v0 / (1.f + __expf(-v0)) * uf.x;
                    v1 = v1 / (1.f + __expf(-v1)) * uf.y;
                    *(__half2*)((__half*)Cv + off) = __floats2half2_rn(v0, v1);
                } else if (MODE == 3) {
                    *(__half2*)((__half*)Cv + off) = __floats2half2_rn(v0, v1);
                } else {
                    if (MODE == 1) {
                        const float* ax = (const float*)aux;
                        v0 += ax[off]; v1 += ax[off+1];
                    }
                    float* C = (float*)Cv + (size_t)blockIdx.y*ksC;
                    float2 o; o.x = v0; o.y = v1;
                    *(float2*)(C + off) = o;
                }
            }
        }
    }
}

// ---------------- instance norm ----------------
__global__ void instnorm_kernel(const float* __restrict__ x) {
    __shared__ float r1[256], r2[256];
    int bm = blockIdx.x, b = bm / MMCH, m = bm % MMCH, tid = threadIdx.x;
    float s = 0.f, s2 = 0.f;
    for (int l = tid; l < LL; l += 256) {
        float v = x[((size_t)b*LL + l)*MMCH + m];
        s += v; s2 += v*v;
    }
    r1[tid] = s; r2[tid] = s2; __syncthreads();
    for (int o = 128; o; o >>= 1) {
        if (tid < o) { r1[tid] += r1[tid+o]; r2[tid] += r2[tid+o]; }
        __syncthreads();
    }
    if (tid == 0) {
        float mu  = r1[0] / (float)LL;
        float var = r2[0] / (float)LL - mu*mu;
        g_mean[bm] = mu;
        g_std[bm]  = sqrtf(var + EPSV);
    }
}

// ---------------- patch embed: grid (112, 4); W_in staged through SMEM ----------------
__global__ void __launch_bounds__(256)
patch_kernel(const float* __restrict__ x, const float* __restrict__ Win,
             const float* __restrict__ bin) {
    __shared__ float ps[NPAT*17];
    __shared__ float ws[128*17];
    int bm = blockIdx.x, b = bm / MMCH, m = bm % MMCH, tid = threadIdx.x;
    float mean = g_mean[bm], inv = 1.f / g_std[bm];
    for (int i = tid; i < NPAT*PP; i += 256) {
        int n = i >> 4, p = i & 15;
        int l = n*SSTR + p; if (l > LL-1) l = LL-1;
        ps[n*17 + p] = (x[((size_t)b*LL + l)*MMCH + m] - mean) * inv;
    }
    const int dloc = tid & 127, ngrp = tid >> 7;
    const int dc0 = blockIdx.y * (DD/128/4);
    for (int dc = dc0; dc < dc0 + DD/128/4; dc++) {
        __syncthreads();
        for (int i = tid; i < 128*PP; i += 256) {
            ws[(i >> 4)*17 + (i & 15)] = Win[(size_t)dc*128*PP + i];
        }
        __syncthreads();
        float w[16];
        #pragma unroll
        for (int p = 0; p < 16; p++) w[p] = ws[dloc*17 + p];
        float bv = bin[dc*128 + dloc];
        #pragma unroll 4
        for (int n0 = 0; n0 < 32; n0++) {
            int n = ngrp*32 + n0;
            float acc = bv;
            #pragma unroll
            for (int p = 0; p < 16; p++) acc += ps[n*17 + p] * w[p];
            g_h[((size_t)(bm*NPAT + n))*DD + dc*128 + dloc] = acc;
        }
    }
}

// ---------------- RMSNorm (fp16 out) ----------------
__global__ void rmsnorm_kernel(const float* __restrict__ in, const float* __restrict__ w,
                               __half* __restrict__ out) {
    __shared__ float red[256];
    int row = blockIdx.x, tid = threadIdx.x;
    const float* r = in + (size_t)row*DD;
    float s = 0.f;
    for (int i = tid; i < DD; i += 256) { float v = r[i]; s += v*v; }
    red[tid] = s; __syncthreads();
    for (int o = 128; o; o >>= 1) { if (tid < o) red[tid] += red[tid+o]; __syncthreads(); }
    float scale = rsqrtf(red[0]/(float)DD + EPSV);
    __half* outr = out + (size_t)row*DD;
    for (int i = tid; i < DD; i += 256) outr[i] = __float2half_rn(r[i]*scale*w[i]);
}

// ---------------- attention (fp16 qkv in, RoPE fused at load, fp16 out) ----------------
#define ROPE_L2C 0.29580585549875576f   // log2(500000)/64
__global__ void attn_kernel() {
    extern __shared__ float sm[];
    float* Qs = sm;
    float* Ks = Qs + 64*128;
    float* Vs = Ks + 128*65;
    float* Ss = Vs + 64*128;
    int bm = blockIdx.x, h = blockIdx.y, kvh = h >> 2;
    int tid = threadIdx.x;
    // Q and K with fused RoPE (pairs d, d+64)
    for (int i = tid; i < 2*64*64; i += 256) {
        int isK = i >= 64*64;
        int j = isK ? i - 64*64 : i;
        int n = j >> 6, d = j & 63;
        size_t base = (size_t)(bm*64 + n)*QKVN + (isK ? 4096 + kvh*HDIM : h*HDIM);
        float t0 = __half2float(g_qkv[base + d]);
        float t1 = __half2float(g_qkv[base + d + 64]);
        float f = exp2f(-ROPE_L2C * (float)d);
        float c, s;
        __sincosf((float)n * f, &s, &c);
        float r0 = t0*c - t1*s;
        float r1 = t1*c + t0*s;
        if (isK) { Ks[d*65 + n] = r0; Ks[(d+64)*65 + n] = r1; }
        else     { Qs[n*128 + d] = r0; Qs[n*128 + d + 64] = r1; }
    }
    for (int i = tid; i < 64*128; i += 256) {
        int n = i >> 7, d = i & 127;
        Vs[i] = __half2float(g_qkv[(size_t)(bm*64 + n)*QKVN + 5120 + kvh*HDIM + d]);
    }
    __syncthreads();
    const float scale = 0.08838834764831845f;
    for (int i = tid; i < 64*64; i += 256) {
        int qi = i >> 6, ki = i & 63;
        float acc;
        if (ki <= qi) {
            acc = 0.f;
            #pragma unroll 8
            for (int d = 0; d < 128; d++) acc += Qs[qi*128 + d]*Ks[d*65 + ki];
            acc *= scale;
        } else acc = -1e9f;
        Ss[qi*65 + ki] = acc;
    }
    __syncthreads();
    if (tid < 64) {
        float mx = -1e30f;
        for (int k = 0; k < 64; k++) mx = fmaxf(mx, Ss[tid*65 + k]);
        float sum = 0.f;
        for (int k = 0; k < 64; k++) { float e = __expf(Ss[tid*65 + k] - mx); Ss[tid*65 + k] = e; sum += e; }
        float inv = 1.f / sum;
        for (int k = 0; k < 64; k++) Ss[tid*65 + k] *= inv;
    }
    __syncthreads();
    for (int i = tid; i < 64*128; i += 256) {
        int qi = i >> 7, d = i & 127;
        float acc = 0.f;
        #pragma unroll 8
        for (int k = 0; k < 64; k++) acc += Ss[qi*65 + k]*Vs[k*128 + d];
        g_o[(size_t)(bm*64 + qi)*DD + h*HDIM + d] = __float2half_rn(acc);
    }
}

// ---------------- FC reduce + head ----------------
__global__ void zreduce_kernel(const float* __restrict__ bfc) {
    int idx = blockIdx.x*256 + threadIdx.x;
    if (idx >= BMSEQ*FCN) return;
    int f = idx & 127, bm = idx >> 7;
    float acc = bfc[f];
    for (int ks = 0; ks < FCSPLIT; ks++) acc += g_zpart[(size_t)ks*16384 + bm*128 + f];
    g_z[idx] = acc;
}

__global__ void head_kernel(const float* __restrict__ Wout, const float* __restrict__ bout,
                            float* __restrict__ out) {
    __shared__ float zr[FCN];
    int bm = blockIdx.x, tid = threadIdx.x;
    if (tid < FCN) {
        float v = g_z[bm*FCN + tid];
        zr[tid] = v > 0.f ? v : 0.01f*v;
    }
    __syncthreads();
    if (tid < PREDN) {
        float acc = bout[tid];
        const float* wr = Wout + (size_t)tid*FCN;
        #pragma unroll 8
        for (int f = 0; f < FCN; f++) acc += zr[f]*wr[f];
        int b = bm / MMCH, m = bm % MMCH;
        out[(size_t)b*(PREDN*MMCH) + tid*MMCH + m] = acc*g_std[bm] + g_mean[bm];
    }
}

// ---------------- host ----------------
extern "C" void kernel_launch(void* const* d_in, const int* in_sizes, int n_in,
                              void* d_out, int out_size) {
    const float* x      = (const float*)d_in[0];
    const float* W_in   = (const float*)d_in[1];
    const float* b_in   = (const float*)d_in[2];
    const float* attn_w = (const float*)d_in[3];
    const float* Wq     = (const float*)d_in[4];
    const float* Wk     = (const float*)d_in[5];
    const float* Wv     = (const float*)d_in[6];
    const float* Wo     = (const float*)d_in[7];
    const float* mlp_w  = (const float*)d_in[8];
    const float* Wg     = (const float*)d_in[9];
    const float* Wu     = (const float*)d_in[10];
    const float* Wd     = (const float*)d_in[11];
    const float* fin_w  = (const float*)d_in[12];
    const float* W_fc   = (const float*)d_in[13];
    const float* b_fc   = (const float*)d_in[14];
    const float* W_out  = (const float*)d_in[15];
    const float* b_out  = (const float*)d_in[16];
    float* out = (float*)d_out;

    float *ph, *pzp;
    __half *phn, *pqkv, *po, *pg, *pu, *pw;
    cudaGetSymbolAddress((void**)&ph,   g_h);
    cudaGetSymbolAddress((void**)&phn,  g_hn);
    cudaGetSymbolAddress((void**)&pqkv, g_qkv);
    cudaGetSymbolAddress((void**)&po,   g_o);
    cudaGetSymbolAddress((void**)&pg,   g_gate);
    cudaGetSymbolAddress((void**)&pu,   g_up);
    cudaGetSymbolAddress((void**)&pzp,  g_zpart);
    cudaGetSymbolAddress((void**)&pw,   g_wtf);

    const int attn_smem = (64*128 + 128*65 + 64*128 + 64*65) * (int)sizeof(float);
    cudaFuncSetAttribute(attn_kernel, cudaFuncAttributeMaxDynamicSharedMemorySize, attn_smem);
    const int gsmem = NSTG * STAGEB;   // 81920
    cudaFuncSetAttribute(hgemm<0>, cudaFuncAttributeMaxDynamicSharedMemorySize, gsmem);
    cudaFuncSetAttribute(hgemm<1>, cudaFuncAttributeMaxDynamicSharedMemorySize, gsmem);
    cudaFuncSetAttribute(hgemm<2>, cudaFuncAttributeMaxDynamicSharedMemorySize, gsmem);
    cudaFuncSetAttribute(hgemm<3>, cudaFuncAttributeMaxDynamicSharedMemorySize, gsmem);

    // weight fp16 convert
    cvtw_a<<<(10485760 + 255)/256, 256>>>((const float4*)Wq, (const float4*)Wk,
                                          (const float4*)Wv, (const float4*)Wo);
    cvtw_b<<<(52428800 + 255)/256, 256>>>((const float4*)Wg, (const float4*)Wu,
                                          (const float4*)Wd, (const float4*)W_fc);
    const __half* tWqkv = pw + WOFF_Q;
    const __half* tWo = pw + WOFF_O;
    const __half* tWg = pw + WOFF_G;  const __half* tWu = pw + WOFF_U;
    const __half* tWd = pw + WOFF_D;  const __half* tWfc = pw + WOFF_FC;

    // RevIN stats
    instnorm_kernel<<<BMSEQ, 256>>>(x);
    // patch embed (112x4 blocks)
    {
        dim3 g(BMSEQ, 4);
        patch_kernel<<<g, 256>>>(x, W_in, b_in);
    }
    // attn RMSNorm -> fp16
    rmsnorm_kernel<<<TOK, 256>>>(ph, attn_w, phn);
    // fused QKV projection (N=6144, fp16 out)
    {
        dim3 g(56*(QKVN/128), 1);
        hgemm<3><<<g, 256, gsmem>>>(phn, DD, tWqkv, DD, pqkv, QKVN, nullptr,
                                    56, QKVN/128, TOK, DD/32, 0, 0, 0);
    }
    // attention (rope fused) -> fp16 o
    {
        dim3 grid(BMSEQ, HHE);
        attn_kernel<<<grid, 256, attn_smem>>>();
    }
    // output proj + residual
    {
        dim3 g(56*32, 1);
        hgemm<1><<<g, 256, gsmem>>>(po, DD, tWo, DD, ph, DD, ph,
                                    56, 32, TOK, DD/32, 0, 0, 0);
    }
    // mlp RMSNorm -> fp16
    rmsnorm_kernel<<<TOK, 256>>>(ph, mlp_w, phn);
    // up proj (fp16 out), gate proj fused silu*up
    {
        dim3 g(56*112, 1);
        hgemm<3><<<g, 256, gsmem>>>(phn, DD, tWu, DD, pu, DFFN, nullptr,
                                    56, 112, TOK, DD/32, 0, 0, 0);
        hgemm<2><<<g, 256, gsmem>>>(phn, DD, tWg, DD, pg, DFFN, pu,
                                    56, 112, TOK, DD/32, 0, 0, 0);
    }
    // down proj + residual
    {
        dim3 g(56*32, 1);
        hgemm<1><<<g, 256, gsmem>>>(pg, DFFN, tWd, DFFN, ph, DD, ph,
                                    56, 32, TOK, DFFN/32, 0, 0, 0);
    }
    // final RMSNorm -> fp16
    rmsnorm_kernel<<<TOK, 256>>>(ph, fin_w, phn);
    // FC head: split-K fp16 GEMM (128 splits)
    {
        dim3 g(1, FCSPLIT);
        hgemm<0><<<g, 256, gsmem>>>(phn, KFC, tWfc, KFC, pzp, 128, nullptr,
                                    1, 1, 112, (KFC/FCSPLIT)/32,
                                    KFC/FCSPLIT, KFC/FCSPLIT, 128*128);
    }
    // reduce + head
    zreduce_kernel<<<(BMSEQ*FCN + 255)/256, 256>>>(b_fc);
    head_kernel<<<BMSEQ, 128>>>(W_out, b_out, out);
}

// round 17
// speedup vs baseline: 1.4697x; 1.0190x over previous
#include <cuda_runtime.h>
#include <cuda_fp16.h>
#include <math.h>
#include <stdint.h>

// ---------------- problem constants ----------------
#define BB   16
#define LL   512
#define MMCH 7
#define PP   16
#define SSTR 8
#define NPAT 64
#define DD   4096
#define HHE  32
#define KVH  8
#define HDIM 128
#define DFFN 14336
#define FCN  128
#define PREDN 96
#define BMSEQ (BB*MMCH)        // 112
#define TOK   (BMSEQ*NPAT)     // 7168
#define KFC   (NPAT*DD)        // 262144
#define QKVN  6144
#define FCSPLIT 128
#define EPSV 1e-5f

// ---------------- scratch ----------------
__device__ float g_mean[BMSEQ];
__device__ float g_std[BMSEQ];
__device__ float g_h [(size_t)TOK*DD];
__device__ __half g_hn[(size_t)TOK*DD];
__device__ __half g_qkv[(size_t)TOK*QKVN];
__device__ __half g_o [(size_t)TOK*DD];
__device__ __half g_gate[(size_t)TOK*DFFN];
__device__ __half g_up  [(size_t)TOK*DFFN];
__device__ float g_zpart[(size_t)FCSPLIT*128*128];
__device__ float g_z[BMSEQ*FCN];
// fp16 weights (0.5 GB); Q,K,V contiguous -> fused QKV GEMM
#define WOFF_Q  0
#define WOFF_K  16777216
#define WOFF_V  20971520
#define WOFF_O  25165824
#define WOFF_G  41943040
#define WOFF_U  100663296
#define WOFF_D  159383552
#define WOFF_FC 218103808
#define WTF_TOTAL 251658240
__device__ __half g_wtf[(size_t)WTF_TOTAL];

__device__ __forceinline__ uint32_t smem_u32(const void* p) {
    uint32_t a;
    asm("{ .reg .u64 t; cvta.to.shared.u64 t, %1; cvt.u32.u64 %0, t; }" : "=r"(a) : "l"(p));
    return a;
}
__device__ __forceinline__ void mma_f16(float c[4], const uint32_t a[4], const uint32_t b[2]) {
    asm volatile("mma.sync.aligned.m16n8k16.row.col.f32.f16.f16.f32 "
        "{%0,%1,%2,%3}, {%4,%5,%6,%7}, {%8,%9}, {%0,%1,%2,%3};"
        : "+f"(c[0]), "+f"(c[1]), "+f"(c[2]), "+f"(c[3])
        : "r"(a[0]), "r"(a[1]), "r"(a[2]), "r"(a[3]), "r"(b[0]), "r"(b[1]));
}
#define LDSM_X4(r0,r1,r2,r3,addr) \
    asm volatile("ldmatrix.sync.aligned.m8n8.x4.shared.b16 {%0,%1,%2,%3}, [%4];" \
        : "=r"(r0), "=r"(r1), "=r"(r2), "=r"(r3) : "r"(addr))
#define CP_ASYNC16(dst, src) \
    asm volatile("cp.async.cg.shared.global [%0], [%1], 16;" :: "r"(dst), "l"(src) : "memory")
#define CP_COMMIT() asm volatile("cp.async.commit_group;" ::: "memory")
#define CP_WAIT2()  asm volatile("cp.async.wait_group 2;" ::: "memory")

// ---------------- weight fp16 convert (2 launches) ----------------
__device__ __forceinline__ void cvt_store(__half2* dst, int i, float4 v) {
    dst[2*i]   = __floats2half2_rn(v.x, v.y);
    dst[2*i+1] = __floats2half2_rn(v.z, v.w);
}
__global__ void cvtw_a(const float4* __restrict__ q, const float4* __restrict__ k,
                       const float4* __restrict__ v, const float4* __restrict__ o) {
    int i = blockIdx.x*256 + threadIdx.x;
    __half2* dst = (__half2*)g_wtf;
    if      (i <  4194304) cvt_store(dst, i, q[i]);
    else if (i <  5242880) cvt_store(dst, i, k[i - 4194304]);
    else if (i <  6291456) cvt_store(dst, i, v[i - 5242880]);
    else if (i < 10485760) cvt_store(dst, i, o[i - 6291456]);
}
__global__ void cvtw_b(const float4* __restrict__ g, const float4* __restrict__ u,
                       const float4* __restrict__ d, const float4* __restrict__ fc) {
    int i = blockIdx.x*256 + threadIdx.x;
    __half2* dst = (__half2*)(g_wtf + WOFF_G);
    if      (i < 14680064) cvt_store(dst, i, g[i]);
    else if (i < 29360128) cvt_store(dst, i, u[i - 14680064]);
    else if (i < 44040192) cvt_store(dst, i, d[i - 29360128]);
    else if (i < 52428800) cvt_store(dst, i, fc[i - 44040192]);
}

// ---------------- fp16 mma GEMM: ldmatrix + cp.async 4-stage ----------------
#define KSH 40
#define TILEA_H (128*KSH)
#define STAGE_H (256*KSH)
#define STAGEB  (STAGE_H*2)
#define NSTG 4

template<int MODE>
__global__ void __launch_bounds__(256, 2)
hgemm(const __half* __restrict__ A, int lda,
      const __half* __restrict__ W, int ldw,
      void* __restrict__ Cv, int ldc,
      const void* __restrict__ aux,
      int Mtiles, int Ntiles, int Mvalid, int kchunks,
      long ksA, long ksW, long ksC)
{
    extern __shared__ __align__(16) __half smh[];
    const uint32_t sb_u = smem_u32(smh);
    const int tid = threadIdx.x;

    A += (size_t)blockIdx.y * ksA;
    W += (size_t)blockIdx.y * ksW;

    int mt, nt;
    {
        const int GM = 16;
        int perg = GM * Ntiles;
        int g = blockIdx.x / perg, rem = blockIdx.x % perg;
        int gm = Mtiles - g*GM; if (gm > GM) gm = GM;
        mt = g*GM + rem % gm;
        nt = rem / gm;
    }

    const __half* gsrc;
    uint32_t srow;
    if (tid < 128) {
        int gr = mt*128 + tid; if (gr >= Mvalid) gr = Mvalid-1;
        gsrc = A + (size_t)gr*lda;
        srow = (uint32_t)tid*(KSH*2);
    } else {
        gsrc = W + (size_t)(nt*128 + (tid-128))*ldw;
        srow = (uint32_t)(TILEA_H*2) + (uint32_t)(tid-128)*(KSH*2);
    }

    const int warp = tid >> 5, lane = tid & 31;
    const int wm = warp & 3, wn = warp >> 2;
    const int gid = lane >> 2, quad = lane & 3;

    uint32_t aAddr[2], bAddr[4];
    #pragma unroll
    for (int f = 0; f < 2; f++)
        aAddr[f] = sb_u + (uint32_t)(((wm*32 + f*16 + (lane & 15))*KSH + (lane >> 4)*8) * 2);
    #pragma unroll
    for (int p = 0; p < 4; p++)
        bAddr[p] = sb_u + (uint32_t)((TILEA_H + (wn*64 + p*16 + (lane & 7) + ((lane >> 4) << 3))*KSH
                                      + ((lane >> 3) & 1)*8) * 2);

    float acc[2][8][4];
    #pragma unroll
    for (int f = 0; f < 2; f++)
        #pragma unroll
        for (int g = 0; g < 8; g++)
            #pragma unroll
            for (int j = 0; j < 4; j++) acc[f][g][j] = 0.f;

    #pragma unroll
    for (int s = 0; s < 3; s++) {
        uint32_t base = sb_u + (uint32_t)s*STAGEB + srow;
        #pragma unroll
        for (int i = 0; i < 4; i++) CP_ASYNC16(base + i*16, gsrc + s*32 + i*8);
        CP_COMMIT();
    }

    int st = 0;
    for (int kc = 0; kc < kchunks; kc++) {
        CP_WAIT2();
        __syncthreads();
        if (kc + 3 < kchunks) {
            int s3 = st + 3; if (s3 >= NSTG) s3 -= NSTG;
            uint32_t base = sb_u + (uint32_t)s3*STAGEB + srow;
            const __half* gk = gsrc + (size_t)(kc+3)*32;
            #pragma unroll
            for (int i = 0; i < 4; i++) CP_ASYNC16(base + i*16, gk + i*8);
        }
        CP_COMMIT();
        const uint32_t stOff = (uint32_t)st*STAGEB;
        #pragma unroll
        for (int ks = 0; ks < 2; ks++) {
            const uint32_t koff = stOff + ks*32;
            uint32_t a[2][4];
            LDSM_X4(a[0][0], a[0][1], a[0][2], a[0][3], aAddr[0] + koff);
            LDSM_X4(a[1][0], a[1][1], a[1][2], a[1][3], aAddr[1] + koff);
            uint32_t b[8][2];
            #pragma unroll
            for (int p = 0; p < 4; p++)
                LDSM_X4(b[2*p][0], b[2*p][1], b[2*p+1][0], b[2*p+1][1], bAddr[p] + koff);
            #pragma unroll
            for (int f = 0; f < 2; f++)
                #pragma unroll
                for (int g = 0; g < 8; g++)
                    mma_f16(acc[f][g], a[f], b[g]);
        }
        st = st + 1; if (st == NSTG) st = 0;
    }

    #pragma unroll
    for (int f = 0; f < 2; f++) {
        int r0 = mt*128 + wm*32 + f*16 + gid;
        #pragma unroll
        for (int g = 0; g < 8; g++) {
            int col = nt*128 + wn*64 + g*8 + 2*quad;
            #pragma unroll
            for (int half_ = 0; half_ < 2; half_++) {
                int row = r0 + half_*8;
                if (row >= Mvalid) continue;
                float v0 = acc[f][g][half_*2 + 0];
                float v1 = acc[f][g][half_*2 + 1];
                size_t off = (size_t)row*ldc + col;
                if (MODE == 2) {
                    __half2 uh = *(const __half2*)((const __half*)aux + off);
                    float2 uf = __half22float2(uh);
                    v0 = v0 / (1.f + __expf(-v0)) * uf.x;
                    v1 = v1 / (1.f + __expf(-v1)) * uf.y;
                    *(__half2*)((__half*)Cv + off) = __floats2half2_rn(v0, v1);
                } else if (MODE == 3) {
                    *(__half2*)((__half*)Cv + off) = __floats2half2_rn(v0, v1);
                } else {
                    if (MODE == 1) {
                        const float* ax = (const float*)aux;
                        v0 += ax[off]; v1 += ax[off+1];
                    }
                    float* C = (float*)Cv + (size_t)blockIdx.y*ksC;
                    float2 o; o.x = v0; o.y = v1;
                    *(float2*)(C + off) = o;
                }
            }
        }
    }
}

// ---------------- instance norm ----------------
__global__ void instnorm_kernel(const float* __restrict__ x) {
    __shared__ float r1[256], r2[256];
    int bm = blockIdx.x, b = bm / MMCH, m = bm % MMCH, tid = threadIdx.x;
    float s = 0.f, s2 = 0.f;
    for (int l = tid; l < LL; l += 256) {
        float v = x[((size_t)b*LL + l)*MMCH + m];
        s += v; s2 += v*v;
    }
    r1[tid] = s; r2[tid] = s2; __syncthreads();
    for (int o = 128; o; o >>= 1) {
        if (tid < o) { r1[tid] += r1[tid+o]; r2[tid] += r2[tid+o]; }
        __syncthreads();
    }
    if (tid == 0) {
        float mu  = r1[0] / (float)LL;
        float var = r2[0] / (float)LL - mu*mu;
        g_mean[bm] = mu;
        g_std[bm]  = sqrtf(var + EPSV);
    }
}

// ---------------- patch embed: grid (112, 4); W_in staged through SMEM ----------------
__global__ void __launch_bounds__(256)
patch_kernel(const float* __restrict__ x, const float* __restrict__ Win,
             const float* __restrict__ bin) {
    __shared__ float ps[NPAT*17];
    __shared__ float ws[128*17];
    int bm = blockIdx.x, b = bm / MMCH, m = bm % MMCH, tid = threadIdx.x;
    float mean = g_mean[bm], inv = 1.f / g_std[bm];
    for (int i = tid; i < NPAT*PP; i += 256) {
        int n = i >> 4, p = i & 15;
        int l = n*SSTR + p; if (l > LL-1) l = LL-1;
        ps[n*17 + p] = (x[((size_t)b*LL + l)*MMCH + m] - mean) * inv;
    }
    const int dloc = tid & 127, ngrp = tid >> 7;
    const int dc0 = blockIdx.y * (DD/128/4);
    for (int dc = dc0; dc < dc0 + DD/128/4; dc++) {
        __syncthreads();
        for (int i = tid; i < 128*PP; i += 256) {
            ws[(i >> 4)*17 + (i & 15)] = Win[(size_t)dc*128*PP + i];
        }
        __syncthreads();
        float w[16];
        #pragma unroll
        for (int p = 0; p < 16; p++) w[p] = ws[dloc*17 + p];
        float bv = bin[dc*128 + dloc];
        #pragma unroll 4
        for (int n0 = 0; n0 < 32; n0++) {
            int n = ngrp*32 + n0;
            float acc = bv;
            #pragma unroll
            for (int p = 0; p < 16; p++) acc += ps[n*17 + p] * w[p];
            g_h[((size_t)(bm*NPAT + n))*DD + dc*128 + dloc] = acc;
        }
    }
}

// ---------------- RMSNorm (fp16 out) ----------------
__global__ void rmsnorm_kernel(const float* __restrict__ in, const float* __restrict__ w,
                               __half* __restrict__ out) {
    __shared__ float red[256];
    int row = blockIdx.x, tid = threadIdx.x;
    const float* r = in + (size_t)row*DD;
    float s = 0.f;
    for (int i = tid; i < DD; i += 256) { float v = r[i]; s += v*v; }
    red[tid] = s; __syncthreads();
    for (int o = 128; o; o >>= 1) { if (tid < o) red[tid] += red[tid+o]; __syncthreads(); }
    float scale = rsqrtf(red[0]/(float)DD + EPSV);
    __half* outr = out + (size_t)row*DD;
    for (int i = tid; i < DD; i += 256) outr[i] = __float2half_rn(r[i]*scale*w[i]);
}

// ---------------- attention: RoPE fused, register-blocked QK & PV ----------------
#define ROPE_L2C 0.29580585549875576f   // log2(500000)/64
#define QP 132   // Qs/Vs pitch (floats)
#define KP 68    // Ks/Ss pitch (floats)
__global__ void __launch_bounds__(256)
attn_kernel() {
    extern __shared__ float sm[];
    float* Qs = sm;                 // [64][QP]
    float* Ks = Qs + 64*QP;         // [128][KP]  (d-major)
    float* Vs = Ks + 128*KP;        // [64][QP]
    float* Ss = Vs + 64*QP;         // [64][KP]
    int bm = blockIdx.x, h = blockIdx.y, kvh = h >> 2;
    int tid = threadIdx.x;
    // stage Q,K with fused RoPE; V straight
    for (int i = tid; i < 2*64*64; i += 256) {
        int isK = i >= 64*64;
        int j = isK ? i - 64*64 : i;
        int n = j >> 6, d = j & 63;
        size_t base = (size_t)(bm*64 + n)*QKVN + (isK ? 4096 + kvh*HDIM : h*HDIM);
        float t0 = __half2float(g_qkv[base + d]);
        float t1 = __half2float(g_qkv[base + d + 64]);
        float f = exp2f(-ROPE_L2C * (float)d);
        float c, s;
        __sincosf((float)n * f, &s, &c);
        float r0 = t0*c - t1*s;
        float r1 = t1*c + t0*s;
        if (isK) { Ks[d*KP + n] = r0; Ks[(d+64)*KP + n] = r1; }
        else     { Qs[n*QP + d] = r0; Qs[n*QP + d + 64] = r1; }
    }
    for (int i = tid; i < 64*128; i += 256) {
        int n = i >> 7, d = i & 127;
        Vs[n*QP + d] = __half2float(g_qkv[(size_t)(bm*64 + n)*QKVN + 5120 + kvh*HDIM + d]);
    }
    __syncthreads();
    // QK^T: 16x16 threads, 4x4 tile each
    {
        const int ty = tid >> 4, tx = tid & 15;
        const int r0 = ty*4, c0 = tx*4;
        float acc[4][4];
        #pragma unroll
        for (int i = 0; i < 4; i++)
            #pragma unroll
            for (int j = 0; j < 4; j++) acc[i][j] = 0.f;
        for (int d = 0; d < 128; d++) {
            float4 kv = *(const float4*)(Ks + d*KP + c0);
            float q0 = Qs[(r0+0)*QP + d];
            float q1 = Qs[(r0+1)*QP + d];
            float q2 = Qs[(r0+2)*QP + d];
            float q3 = Qs[(r0+3)*QP + d];
            acc[0][0] += q0*kv.x; acc[0][1] += q0*kv.y; acc[0][2] += q0*kv.z; acc[0][3] += q0*kv.w;
            acc[1][0] += q1*kv.x; acc[1][1] += q1*kv.y; acc[1][2] += q1*kv.z; acc[1][3] += q1*kv.w;
            acc[2][0] += q2*kv.x; acc[2][1] += q2*kv.y; acc[2][2] += q2*kv.z; acc[2][3] += q2*kv.w;
            acc[3][0] += q3*kv.x; acc[3][1] += q3*kv.y; acc[3][2] += q3*kv.z; acc[3][3] += q3*kv.w;
        }
        const float scale = 0.08838834764831845f;
        #pragma unroll
        for (int i = 0; i < 4; i++)
            #pragma unroll
            for (int j = 0; j < 4; j++) {
                int r = r0+i, c = c0+j;
                Ss[r*KP + c] = (c <= r) ? acc[i][j]*scale : -1e9f;
            }
    }
    __syncthreads();
    // softmax: 4 threads per row, quad shuffle reduce
    {
        const int row = tid >> 2, q = tid & 3;
        float mx = -1e30f;
        for (int c = q; c < 64; c += 4) mx = fmaxf(mx, Ss[row*KP + c]);
        mx = fmaxf(mx, __shfl_xor_sync(0xffffffffu, mx, 1));
        mx = fmaxf(mx, __shfl_xor_sync(0xffffffffu, mx, 2));
        float sum = 0.f;
        for (int c = q; c < 64; c += 4) {
            float e = __expf(Ss[row*KP + c] - mx);
            Ss[row*KP + c] = e;
            sum += e;
        }
        sum += __shfl_xor_sync(0xffffffffu, sum, 1);
        sum += __shfl_xor_sync(0xffffffffu, sum, 2);
        float inv = 1.f / sum;
        for (int c = q; c < 64; c += 4) Ss[row*KP + c] *= inv;
    }
    __syncthreads();
    // PV: 16x16 threads, 4 rows x 8 cols each
    {
        const int ty = tid >> 4, tx = tid & 15;
        const int r0 = ty*4, c0 = tx*8;
        float acc[4][8];
        #pragma unroll
        for (int i = 0; i < 4; i++)
            #pragma unroll
            for (int j = 0; j < 8; j++) acc[i][j] = 0.f;
        for (int k = 0; k < 64; k++) {
            float4 v0 = *(const float4*)(Vs + k*QP + c0);
            float4 v1 = *(const float4*)(Vs + k*QP + c0 + 4);
            float p0 = Ss[(r0+0)*KP + k];
            float p1 = Ss[(r0+1)*KP + k];
            float p2 = Ss[(r0+2)*KP + k];
            float p3 = Ss[(r0+3)*KP + k];
            acc[0][0]+=p0*v0.x; acc[0][1]+=p0*v0.y; acc[0][2]+=p0*v0.z; acc[0][3]+=p0*v0.w;
            acc[0][4]+=p0*v1.x; acc[0][5]+=p0*v1.y; acc[0][6]+=p0*v1.z; acc[0][7]+=p0*v1.w;
            acc[1][0]+=p1*v0.x; acc[1][1]+=p1*v0.y; acc[1][2]+=p1*v0.z; acc[1][3]+=p1*v0.w;
            acc[1][4]+=p1*v1.x; acc[1][5]+=p1*v1.y; acc[1][6]+=p1*v1.z; acc[1][7]+=p1*v1.w;
            acc[2][0]+=p2*v0.x; acc[2][1]+=p2*v0.y; acc[2][2]+=p2*v0.z; acc[2][3]+=p2*v0.w;
            acc[2][4]+=p2*v1.x; acc[2][5]+=p2*v1.y; acc[2][6]+=p2*v1.z; acc[2][7]+=p2*v1.w;
            acc[3][0]+=p3*v0.x; acc[3][1]+=p3*v0.y; acc[3][2]+=p3*v0.z; acc[3][3]+=p3*v0.w;
            acc[3][4]+=p3*v1.x; acc[3][5]+=p3*v1.y; acc[3][6]+=p3*v1.z; acc[3][7]+=p3*v1.w;
        }
        #pragma unroll
        for (int i = 0; i < 4; i++) {
            __half* op = g_o + (size_t)(bm*64 + r0 + i)*DD + h*HDIM + c0;
            #pragma unroll
            for (int j = 0; j < 8; j += 2)
                *(__half2*)(op + j) = __floats2half2_rn(acc[i][j], acc[i][j+1]);
        }
    }
}

// ---------------- FC reduce + head ----------------
__global__ void zreduce_kernel(const float* __restrict__ bfc) {
    int idx = blockIdx.x*256 + threadIdx.x;
    if (idx >= BMSEQ*FCN) return;
    int f = idx & 127, bm = idx >> 7;
    float acc = bfc[f];
    for (int ks = 0; ks < FCSPLIT; ks++) acc += g_zpart[(size_t)ks*16384 + bm*128 + f];
    g_z[idx] = acc;
}

__global__ void head_kernel(const float* __restrict__ Wout, const float* __restrict__ bout,
                            float* __restrict__ out) {
    __shared__ float zr[FCN];
    int bm = blockIdx.x, tid = threadIdx.x;
    if (tid < FCN) {
        float v = g_z[bm*FCN + tid];
        zr[tid] = v > 0.f ? v : 0.01f*v;
    }
    __syncthreads();
    if (tid < PREDN) {
        float acc = bout[tid];
        const float* wr = Wout + (size_t)tid*FCN;
        #pragma unroll 8
        for (int f = 0; f < FCN; f++) acc += zr[f]*wr[f];
        int b = bm / MMCH, m = bm % MMCH;
        out[(size_t)b*(PREDN*MMCH) + tid*MMCH + m] = acc*g_std[bm] + g_mean[bm];
    }
}

// ---------------- host ----------------
extern "C" void kernel_launch(void* const* d_in, const int* in_sizes, int n_in,
                              void* d_out, int out_size) {
    const float* x      = (const float*)d_in[0];
    const float* W_in   = (const float*)d_in[1];
    const float* b_in   = (const float*)d_in[2];
    const float* attn_w = (const float*)d_in[3];
    const float* Wq     = (const float*)d_in[4];
    const float* Wk     = (const float*)d_in[5];
    const float* Wv     = (const float*)d_in[6];
    const float* Wo     = (const float*)d_in[7];
    const float* mlp_w  = (const float*)d_in[8];
    const float* Wg     = (const float*)d_in[9];
    const float* Wu     = (const float*)d_in[10];
    const float* Wd     = (const float*)d_in[11];
    const float* fin_w  = (const float*)d_in[12];
    const float* W_fc   = (const float*)d_in[13];
    const float* b_fc   = (const float*)d_in[14];
    const float* W_out  = (const float*)d_in[15];
    const float* b_out  = (const float*)d_in[16];
    float* out = (float*)d_out;

    float *ph, *pzp;
    __half *phn, *pqkv, *po, *pg, *pu, *pw;
    cudaGetSymbolAddress((void**)&ph,   g_h);
    cudaGetSymbolAddress((void**)&phn,  g_hn);
    cudaGetSymbolAddress((void**)&pqkv, g_qkv);
    cudaGetSymbolAddress((void**)&po,   g_o);
    cudaGetSymbolAddress((void**)&pg,   g_gate);
    cudaGetSymbolAddress((void**)&pu,   g_up);
    cudaGetSymbolAddress((void**)&pzp,  g_zpart);
    cudaGetSymbolAddress((void**)&pw,   g_wtf);

    const int attn_smem = (64*QP + 128*KP + 64*QP + 64*KP) * (int)sizeof(float);  // 119808
    cudaFuncSetAttribute(attn_kernel, cudaFuncAttributeMaxDynamicSharedMemorySize, attn_smem);
    const int gsmem = NSTG * STAGEB;   // 81920
    cudaFuncSetAttribute(hgemm<0>, cudaFuncAttributeMaxDynamicSharedMemorySize, gsmem);
    cudaFuncSetAttribute(hgemm<1>, cudaFuncAttributeMaxDynamicSharedMemorySize, gsmem);
    cudaFuncSetAttribute(hgemm<2>, cudaFuncAttributeMaxDynamicSharedMemorySize, gsmem);
    cudaFuncSetAttribute(hgemm<3>, cudaFuncAttributeMaxDynamicSharedMemorySize, gsmem);

    // weight fp16 convert
    cvtw_a<<<(10485760 + 255)/256, 256>>>((const float4*)Wq, (const float4*)Wk,
                                          (const float4*)Wv, (const float4*)Wo);
    cvtw_b<<<(52428800 + 255)/256, 256>>>((const float4*)Wg, (const float4*)Wu,
                                          (const float4*)Wd, (const float4*)W_fc);
    const __half* tWqkv = pw + WOFF_Q;
    const __half* tWo = pw + WOFF_O;
    const __half* tWg = pw + WOFF_G;  const __half* tWu = pw + WOFF_U;
    const __half* tWd = pw + WOFF_D;  const __half* tWfc = pw + WOFF_FC;

    // RevIN stats
    instnorm_kernel<<<BMSEQ, 256>>>(x);
    // patch embed (112x4 blocks)
    {
        dim3 g(BMSEQ, 4);
        patch_kernel<<<g, 256>>>(x, W_in, b_in);
    }
    // attn RMSNorm -> fp16
    rmsnorm_kernel<<<TOK, 256>>>(ph, attn_w, phn);
    // fused QKV projection (N=6144, fp16 out)
    {
        dim3 g(56*(QKVN/128), 1);
        hgemm<3><<<g, 256, gsmem>>>(phn, DD, tWqkv, DD, pqkv, QKVN, nullptr,
                                    56, QKVN/128, TOK, DD/32, 0, 0, 0);
    }
    // attention (rope fused, register-blocked) -> fp16 o
    {
        dim3 grid(BMSEQ, HHE);
        attn_kernel<<<grid, 256, attn_smem>>>();
    }
    // output proj + residual
    {
        dim3 g(56*32, 1);
        hgemm<1><<<g, 256, gsmem>>>(po, DD, tWo, DD, ph, DD, ph,
                                    56, 32, TOK, DD/32, 0, 0, 0);
    }
    // mlp RMSNorm -> fp16
    rmsnorm_kernel<<<TOK, 256>>>(ph, mlp_w, phn);
    // up proj (fp16 out), gate proj fused silu*up
    {
        dim3 g(56*112, 1);
        hgemm<3><<<g, 256, gsmem>>>(phn, DD, tWu, DD, pu, DFFN, nullptr,
                                    56, 112, TOK, DD/32, 0, 0, 0);
        hgemm<2><<<g, 256, gsmem>>>(phn, DD, tWg, DD, pg, DFFN, pu,
                                    56, 112, TOK, DD/32, 0, 0, 0);
    }
    // down proj + residual
    {
        dim3 g(56*32, 1);
        hgemm<1><<<g, 256, gsmem>>>(pg, DFFN, tWd, DFFN, ph, DD, ph,
                                    56, 32, TOK, DFFN/32, 0, 0, 0);
    }
    // final RMSNorm -> fp16
    rmsnorm_kernel<<<TOK, 256>>>(ph, fin_w, phn);
    // FC head: split-K fp16 GEMM (128 splits)
    {
        dim3 g(1, FCSPLIT);
        hgemm<0><<<g, 256, gsmem>>>(phn, KFC, tWfc, KFC, pzp, 128, nullptr,
                                    1, 1, 112, (KFC/FCSPLIT)/32,
                                    KFC/FCSPLIT, KFC/FCSPLIT, 128*128);
    }
    // reduce + head
    zreduce_kernel<<<(BMSEQ*FCN + 255)/256, 256>>>(b_fc);
    head_kernel<<<BMSEQ, 128>>>(W_out, b_out, out);
}